// round 1
// baseline (speedup 1.0000x reference)
#include <cuda_runtime.h>
#include <cuda_bf16.h>

// ---------------------------------------------------------------------------
// SelfAttention: x[4,2048,1024] fp32, w_qkv[1024,3072], w_out[1024,1024]
// Pipeline:
//   K1: GEMM (tf32 mma.sync)  x @ w_qkv -> scatter into g_q/g_k/g_v [bh][t][dh]
//   K2: flash attention (tf32 mma.sync), online softmax, -> g_o [8192][1024]
//   K3: GEMM (tf32 mma.sync)  g_o @ w_out -> d_out
// ---------------------------------------------------------------------------

#define HEADS   16
#define DH      64
#define SEQT    2048
#define BATCH   4
#define DMODEL  1024
#define BHEADS  (BATCH * HEADS)   // 64
#define MROWS   (BATCH * SEQT)    // 8192

__device__ float g_q[(size_t)BHEADS * SEQT * DH];
__device__ float g_k[(size_t)BHEADS * SEQT * DH];
__device__ float g_v[(size_t)BHEADS * SEQT * DH];
__device__ float g_o[(size_t)MROWS * DMODEL];

__device__ __forceinline__ float tf32r(float f) {
    unsigned u;
    asm("cvt.rna.tf32.f32 %0, %1;" : "=r"(u) : "f"(f));
    return __uint_as_float(u);
}
__device__ __forceinline__ float4 tf32r4(float4 v) {
    return make_float4(tf32r(v.x), tf32r(v.y), tf32r(v.z), tf32r(v.w));
}
__device__ __forceinline__ unsigned fb(float f) { return __float_as_uint(f); }

// D += A(16x8) * B(8x8), tf32 inputs, f32 accumulate
__device__ __forceinline__ void mma_tf32(float* c, const unsigned* a,
                                         unsigned b0, unsigned b1) {
    asm volatile(
        "mma.sync.aligned.m16n8k8.row.col.f32.tf32.tf32.f32 "
        "{%0,%1,%2,%3},{%4,%5,%6,%7},{%8,%9},{%0,%1,%2,%3};\n"
        : "+f"(c[0]), "+f"(c[1]), "+f"(c[2]), "+f"(c[3])
        : "r"(a[0]), "r"(a[1]), "r"(a[2]), "r"(a[3]), "r"(b0), "r"(b1));
}

// ---------------------------------------------------------------------------
// Generic tf32 GEMM: C[M,N] = A[M,K] @ B[K,N]
//   BM=128, BN=64, BK=32, 256 threads, 8 warps (4 x 2), warp tile 32x32.
//   mode 0: plain store to C.
//   mode 1: QKV scatter into g_q/g_k/g_v with [bh][t][dh] layout.
//   A == nullptr means "use g_o as A" (for the output projection).
// ---------------------------------------------------------------------------
#define BM 128
#define BN 64
#define BK 32
#define ASTR 36   // 128*36 floats, bank-conflict-free frag loads, 16B-aligned rows
#define BSTR 68

__global__ __launch_bounds__(256) void gemm_tf32(
    const float* __restrict__ A, const float* __restrict__ B,
    float* __restrict__ C, int M, int N, int K, int mode)
{
    __shared__ float As[BM * ASTR];
    __shared__ float Bs[BK * BSTR];

    const float* Ap = A ? A : g_o;
    const int tid = threadIdx.x;
    const int bn = blockIdx.x, bm = blockIdx.y;
    const int lane = tid & 31, wid = tid >> 5;
    const int wm = wid >> 1, wn = wid & 1;

    float acc[2][4][4];
#pragma unroll
    for (int mt = 0; mt < 2; mt++)
#pragma unroll
        for (int nt = 0; nt < 4; nt++)
#pragma unroll
            for (int i = 0; i < 4; i++) acc[mt][nt][i] = 0.f;

    const int nkt = K / BK;
    for (int kt = 0; kt < nkt; kt++) {
        // load A tile 128x32 (16 floats/thread, 4 x float4), convert to tf32
#pragma unroll
        for (int p = 0; p < 4; p++) {
            int r = p * 32 + (tid >> 3);
            int c = (tid & 7) * 4;
            float4 v = *(const float4*)(Ap + (size_t)(bm * BM + r) * K + kt * BK + c);
            *(float4*)&As[r * ASTR + c] = tf32r4(v);
        }
        // load B tile 32x64 (8 floats/thread, 2 x float4)
#pragma unroll
        for (int p = 0; p < 2; p++) {
            int kk = p * 16 + (tid >> 4);
            int c = (tid & 15) * 4;
            float4 v = *(const float4*)(B + (size_t)(kt * BK + kk) * N + bn * BN + c);
            *(float4*)&Bs[kk * BSTR + c] = tf32r4(v);
        }
        __syncthreads();

#pragma unroll
        for (int kc = 0; kc < 4; kc++) {
            const int k0 = kc * 8;
            unsigned a[2][4];
#pragma unroll
            for (int mt = 0; mt < 2; mt++) {
                int r = wm * 32 + mt * 16 + (lane >> 2);
                int kk = k0 + (lane & 3);
                a[mt][0] = fb(As[r * ASTR + kk]);
                a[mt][1] = fb(As[(r + 8) * ASTR + kk]);
                a[mt][2] = fb(As[r * ASTR + kk + 4]);
                a[mt][3] = fb(As[(r + 8) * ASTR + kk + 4]);
            }
#pragma unroll
            for (int nt = 0; nt < 4; nt++) {
                int cc = wn * 32 + nt * 8 + (lane >> 2);
                unsigned b0 = fb(Bs[(k0 + (lane & 3)) * BSTR + cc]);
                unsigned b1 = fb(Bs[(k0 + 4 + (lane & 3)) * BSTR + cc]);
                mma_tf32(acc[0][nt], a[0], b0, b1);
                mma_tf32(acc[1][nt], a[1], b0, b1);
            }
        }
        __syncthreads();
    }

    // epilogue
#pragma unroll
    for (int mt = 0; mt < 2; mt++) {
#pragma unroll
        for (int nt = 0; nt < 4; nt++) {
            int rbase = bm * BM + wm * 32 + mt * 16 + (lane >> 2);
            int cbase = bn * BN + wn * 32 + nt * 8 + 2 * (lane & 3);
#pragma unroll
            for (int i = 0; i < 4; i++) {
                int rr = rbase + ((i >= 2) ? 8 : 0);
                int cc = cbase + (i & 1);
                float v = acc[mt][nt][i];
                if (mode == 0) {
                    C[(size_t)rr * N + cc] = v;
                } else {
                    int b = rr >> 11, t = rr & 2047;
                    int which = cc >> 10, rem = cc & 1023;
                    int h = rem >> 6, dd = rem & 63;
                    float* dst = (which == 0) ? g_q : ((which == 1) ? g_k : g_v);
                    dst[(((size_t)(b * HEADS + h)) * SEQT + t) * DH + dd] = v;
                }
            }
        }
    }
}

// ---------------------------------------------------------------------------
// Flash attention, tf32 mma. Grid (bh=64, qtile=32). Block = 128 threads
// (4 warps). Each warp owns 16 query rows; each block a 64-query tile.
// Streams over 32 kv tiles of 64 keys. Q/P/accumulators resident in regs;
// K/V/P staged in dynamic smem (stride 68 floats => conflict-free K frags).
// ---------------------------------------------------------------------------
#define KSTR 68

__global__ __launch_bounds__(128) void flash_attn() {
    extern __shared__ float sm[];
    float* Ks = sm;
    float* Vs = sm + 64 * KSTR;
    float* Ps = sm + 2 * 64 * KSTR;

    const int bh = blockIdx.x, qt = blockIdx.y;
    const int tid = threadIdx.x, lane = tid & 31, w = tid >> 5;

    const float* Qg = g_q + ((size_t)bh * SEQT + qt * 64) * DH;
    const float* Kg = g_k + (size_t)bh * SEQT * DH;
    const float* Vg = g_v + (size_t)bh * SEQT * DH;

    // stage Q tile into Ps, then keep per-warp fragments in registers
#pragma unroll
    for (int p = 0; p < 8; p++) {
        int r = p * 8 + (tid >> 4);
        int c = (tid & 15) * 4;
        float4 v = *(const float4*)(Qg + (size_t)r * DH + c);
        *(float4*)&Ps[r * KSTR + c] = tf32r4(v);
    }
    __syncthreads();

    unsigned aQ[8][4];
    const int r0 = w * 16 + (lane >> 2);
#pragma unroll
    for (int kc = 0; kc < 8; kc++) {
        int kk = kc * 8 + (lane & 3);
        aQ[kc][0] = fb(Ps[r0 * KSTR + kk]);
        aQ[kc][1] = fb(Ps[(r0 + 8) * KSTR + kk]);
        aQ[kc][2] = fb(Ps[r0 * KSTR + kk + 4]);
        aQ[kc][3] = fb(Ps[(r0 + 8) * KSTR + kk + 4]);
    }
    __syncthreads();

    float mrow0 = -1e30f, mrow1 = -1e30f;
    float lrow0 = 0.f, lrow1 = 0.f;
    float o[8][4];
#pragma unroll
    for (int nt = 0; nt < 8; nt++)
#pragma unroll
        for (int i = 0; i < 4; i++) o[nt][i] = 0.f;

    const float SCALE = 0.03125f;  // 1024^-0.5 (full model dim, per reference)

    for (int j = 0; j < 32; j++) {
        // load K and V 64x64 tiles
#pragma unroll
        for (int p = 0; p < 8; p++) {
            int r = p * 8 + (tid >> 4);
            int c = (tid & 15) * 4;
            size_t off = (size_t)(j * 64 + r) * DH + c;
            *(float4*)&Ks[r * KSTR + c] = tf32r4(*(const float4*)(Kg + off));
            *(float4*)&Vs[r * KSTR + c] = tf32r4(*(const float4*)(Vg + off));
        }
        __syncthreads();

        // S = Q @ K^T  (64x64 per block; this warp: rows [16w,16w+16))
        float s[8][4];
#pragma unroll
        for (int nt = 0; nt < 8; nt++) {
            s[nt][0] = s[nt][1] = s[nt][2] = s[nt][3] = 0.f;
        }
#pragma unroll
        for (int kc = 0; kc < 8; kc++) {
            int kd = kc * 8 + (lane & 3);
#pragma unroll
            for (int nt = 0; nt < 8; nt++) {
                int key = nt * 8 + (lane >> 2);
                unsigned b0 = fb(Ks[key * KSTR + kd]);
                unsigned b1 = fb(Ks[key * KSTR + kd + 4]);
                mma_tf32(s[nt], aQ[kc], b0, b1);
            }
        }

        // online softmax: rows r0 (regs 0,1) and r0+8 (regs 2,3)
        float mx0 = mrow0, mx1 = mrow1;
#pragma unroll
        for (int nt = 0; nt < 8; nt++) {
            s[nt][0] *= SCALE; s[nt][1] *= SCALE;
            s[nt][2] *= SCALE; s[nt][3] *= SCALE;
            mx0 = fmaxf(mx0, fmaxf(s[nt][0], s[nt][1]));
            mx1 = fmaxf(mx1, fmaxf(s[nt][2], s[nt][3]));
        }
        mx0 = fmaxf(mx0, __shfl_xor_sync(0xffffffffu, mx0, 1));
        mx0 = fmaxf(mx0, __shfl_xor_sync(0xffffffffu, mx0, 2));
        mx1 = fmaxf(mx1, __shfl_xor_sync(0xffffffffu, mx1, 1));
        mx1 = fmaxf(mx1, __shfl_xor_sync(0xffffffffu, mx1, 2));

        float alpha0 = __expf(mrow0 - mx0);
        float alpha1 = __expf(mrow1 - mx1);
        mrow0 = mx0; mrow1 = mx1;

        float sum0 = 0.f, sum1 = 0.f;
#pragma unroll
        for (int nt = 0; nt < 8; nt++) {
            float p0 = __expf(s[nt][0] - mx0);
            float p1 = __expf(s[nt][1] - mx0);
            float p2 = __expf(s[nt][2] - mx1);
            float p3 = __expf(s[nt][3] - mx1);
            sum0 += p0 + p1;
            sum1 += p2 + p3;
            int cb = nt * 8 + 2 * (lane & 3);
            Ps[r0 * KSTR + cb]       = tf32r(p0);
            Ps[r0 * KSTR + cb + 1]   = tf32r(p1);
            Ps[(r0 + 8) * KSTR + cb]     = tf32r(p2);
            Ps[(r0 + 8) * KSTR + cb + 1] = tf32r(p3);
            o[nt][0] *= alpha0; o[nt][1] *= alpha0;
            o[nt][2] *= alpha1; o[nt][3] *= alpha1;
        }
        sum0 += __shfl_xor_sync(0xffffffffu, sum0, 1);
        sum0 += __shfl_xor_sync(0xffffffffu, sum0, 2);
        sum1 += __shfl_xor_sync(0xffffffffu, sum1, 1);
        sum1 += __shfl_xor_sync(0xffffffffu, sum1, 2);
        lrow0 = lrow0 * alpha0 + sum0;
        lrow1 = lrow1 * alpha1 + sum1;

        __syncwarp();  // P strip is per-warp: writes above, reads below

        // O += P @ V
#pragma unroll
        for (int kc = 0; kc < 8; kc++) {
            int kk = kc * 8 + (lane & 3);
            unsigned aP[4];
            aP[0] = fb(Ps[r0 * KSTR + kk]);
            aP[1] = fb(Ps[(r0 + 8) * KSTR + kk]);
            aP[2] = fb(Ps[r0 * KSTR + kk + 4]);
            aP[3] = fb(Ps[(r0 + 8) * KSTR + kk + 4]);
#pragma unroll
            for (int nt = 0; nt < 8; nt++) {
                int cc = nt * 8 + (lane >> 2);
                unsigned b0 = fb(Vs[kk * KSTR + cc]);
                unsigned b1 = fb(Vs[(kk + 4) * KSTR + cc]);
                mma_tf32(o[nt], aP, b0, b1);
            }
        }
        __syncthreads();  // protect K/V smem before next tile's loads
    }

    // epilogue: normalize and write to g_o [8192][1024] at col h*64+...
    float inv0 = 1.f / lrow0, inv1 = 1.f / lrow1;
    int b = bh >> 4, h = bh & 15;
    size_t row0 = (size_t)b * SEQT + qt * 64 + r0;
#pragma unroll
    for (int nt = 0; nt < 8; nt++) {
        int cc = h * DH + nt * 8 + 2 * (lane & 3);
        g_o[row0 * DMODEL + cc]           = o[nt][0] * inv0;
        g_o[row0 * DMODEL + cc + 1]       = o[nt][1] * inv0;
        g_o[(row0 + 8) * DMODEL + cc]     = o[nt][2] * inv1;
        g_o[(row0 + 8) * DMODEL + cc + 1] = o[nt][3] * inv1;
    }
}

// ---------------------------------------------------------------------------
extern "C" void kernel_launch(void* const* d_in, const int* in_sizes, int n_in,
                              void* d_out, int out_size) {
    const float* x     = (const float*)d_in[0];  // [4,2048,1024]
    const float* w_qkv = (const float*)d_in[1];  // [1024,3072]
    const float* w_out = (const float*)d_in[2];  // [1024,1024]
    float* out = (float*)d_out;                  // [4,2048,1024]

    // K1: QKV projection with head-scatter epilogue
    gemm_tf32<<<dim3(3 * DMODEL / BN, MROWS / BM), 256>>>(
        x, w_qkv, nullptr, MROWS, 3 * DMODEL, DMODEL, 1);

    // K2: flash attention (52,224 B dynamic smem)
    cudaFuncSetAttribute(flash_attn, cudaFuncAttributeMaxDynamicSharedMemorySize,
                         64 * 1024);
    flash_attn<<<dim3(BHEADS, SEQT / 64), 128, 3 * 64 * KSTR * sizeof(float)>>>();

    // K3: output projection
    gemm_tf32<<<dim3(DMODEL / BN, MROWS / BM), 256>>>(
        nullptr, w_out, out, MROWS, DMODEL, DMODEL, 0);
}

// round 2
// speedup vs baseline: 1.1576x; 1.1576x over previous
#include <cuda_runtime.h>
#include <cuda_bf16.h>

#define HEADS   16
#define DH      64
#define SEQT    2048
#define BATCH   4
#define DMODEL  1024
#define BHEADS  (BATCH * HEADS)   // 64
#define MROWS   (BATCH * SEQT)    // 8192

__device__ float g_q[(size_t)BHEADS * SEQT * DH];
__device__ float g_k[(size_t)BHEADS * SEQT * DH];
__device__ float g_v[(size_t)BHEADS * SEQT * DH];
__device__ float g_o[(size_t)MROWS * DMODEL];

__device__ __forceinline__ float tf32r(float f) {
    unsigned u;
    asm("cvt.rna.tf32.f32 %0, %1;" : "=r"(u) : "f"(f));
    return __uint_as_float(u);
}
__device__ __forceinline__ float4 tf32r4(float4 v) {
    return make_float4(tf32r(v.x), tf32r(v.y), tf32r(v.z), tf32r(v.w));
}
__device__ __forceinline__ unsigned fb(float f) { return __float_as_uint(f); }

__device__ __forceinline__ void mma_tf32(float* c, const unsigned* a,
                                         unsigned b0, unsigned b1) {
    asm volatile(
        "mma.sync.aligned.m16n8k8.row.col.f32.tf32.tf32.f32 "
        "{%0,%1,%2,%3},{%4,%5,%6,%7},{%8,%9},{%0,%1,%2,%3};\n"
        : "+f"(c[0]), "+f"(c[1]), "+f"(c[2]), "+f"(c[3])
        : "r"(a[0]), "r"(a[1]), "r"(a[2]), "r"(a[3]), "r"(b0), "r"(b1));
}

// ---------------------------------------------------------------------------
// GEMM v2: C[M,N] = A[M,K] @ B[K,N].  BM=BN=128, BK=16, 128 threads (4 warps
// 2x2), warp tile 64x64 (mt=4, nt=8). Double-buffered smem, register-staged
// global prefetch with RNA tf32 convert on the STS path.
//   mode 0: plain store.  mode 1: QKV head-scatter.  A==nullptr -> use g_o.
// ---------------------------------------------------------------------------
#define BM 128
#define BN 128
#define BK 16
#define ASTR 20    // 20r+k mod 32: conflict-free frag loads
#define BSTR 136   // 8k+c mod 32: conflict-free frag loads

__global__ __launch_bounds__(128) void gemm_tf32(
    const float* __restrict__ A, const float* __restrict__ B,
    float* __restrict__ C, int M, int N, int K, int mode)
{
    __shared__ float As[2][BM * ASTR];   // 20.0 KB
    __shared__ float Bs[2][BK * BSTR];   // 17.0 KB

    const float* Ap = A ? A : g_o;
    const int tid = threadIdx.x;
    const int bn = blockIdx.x, bm = blockIdx.y;
    const int lane = tid & 31, wid = tid >> 5;
    const int wm = wid >> 1, wn = wid & 1;

    float acc[4][8][4];
#pragma unroll
    for (int mt = 0; mt < 4; mt++)
#pragma unroll
        for (int nt = 0; nt < 8; nt++)
#pragma unroll
            for (int i = 0; i < 4; i++) acc[mt][nt][i] = 0.f;

    const int arow = tid >> 2, acol = (tid & 3) * 4;    // A tile coords
    const int brow = tid >> 5, bcol = (tid & 31) * 4;   // B tile coords

    float4 rA[4], rB[4];
    // prologue: tile 0
#pragma unroll
    for (int p = 0; p < 4; p++)
        rA[p] = *(const float4*)(Ap + (size_t)(bm * BM + p * 32 + arow) * K + acol);
#pragma unroll
    for (int p = 0; p < 4; p++)
        rB[p] = *(const float4*)(B + (size_t)(p * 4 + brow) * N + bn * BN + bcol);
#pragma unroll
    for (int p = 0; p < 4; p++)
        *(float4*)&As[0][(p * 32 + arow) * ASTR + acol] = tf32r4(rA[p]);
#pragma unroll
    for (int p = 0; p < 4; p++)
        *(float4*)&Bs[0][(p * 4 + brow) * BSTR + bcol] = tf32r4(rB[p]);
    __syncthreads();

    const int nkt = K / BK;
    for (int kt = 0; kt < nkt; kt++) {
        const int cur = kt & 1;
        const bool pf = (kt + 1 < nkt);
        if (pf) {
#pragma unroll
            for (int p = 0; p < 4; p++)
                rA[p] = *(const float4*)(Ap + (size_t)(bm * BM + p * 32 + arow) * K
                                         + (kt + 1) * BK + acol);
#pragma unroll
            for (int p = 0; p < 4; p++)
                rB[p] = *(const float4*)(B + (size_t)((kt + 1) * BK + p * 4 + brow) * N
                                         + bn * BN + bcol);
        }

#pragma unroll
        for (int kc = 0; kc < 2; kc++) {
            unsigned a[4][4];
            const int kk = kc * 8 + (lane & 3);
#pragma unroll
            for (int mt = 0; mt < 4; mt++) {
                int r = wm * 64 + mt * 16 + (lane >> 2);
                a[mt][0] = fb(As[cur][r * ASTR + kk]);
                a[mt][1] = fb(As[cur][(r + 8) * ASTR + kk]);
                a[mt][2] = fb(As[cur][r * ASTR + kk + 4]);
                a[mt][3] = fb(As[cur][(r + 8) * ASTR + kk + 4]);
            }
            unsigned b[8][2];
#pragma unroll
            for (int nt = 0; nt < 8; nt++) {
                int cc = wn * 64 + nt * 8 + (lane >> 2);
                b[nt][0] = fb(Bs[cur][kk * BSTR + cc]);
                b[nt][1] = fb(Bs[cur][(kk + 4) * BSTR + cc]);
            }
#pragma unroll
            for (int mt = 0; mt < 4; mt++)
#pragma unroll
                for (int nt = 0; nt < 8; nt++)
                    mma_tf32(acc[mt][nt], a[mt], b[nt][0], b[nt][1]);
        }

        if (pf) {
#pragma unroll
            for (int p = 0; p < 4; p++)
                *(float4*)&As[cur ^ 1][(p * 32 + arow) * ASTR + acol] = tf32r4(rA[p]);
#pragma unroll
            for (int p = 0; p < 4; p++)
                *(float4*)&Bs[cur ^ 1][(p * 4 + brow) * BSTR + bcol] = tf32r4(rB[p]);
        }
        __syncthreads();
    }

    // epilogue
#pragma unroll
    for (int mt = 0; mt < 4; mt++) {
#pragma unroll
        for (int nt = 0; nt < 8; nt++) {
            int rbase = bm * BM + wm * 64 + mt * 16 + (lane >> 2);
            int cbase = bn * BN + wn * 64 + nt * 8 + 2 * (lane & 3);
#pragma unroll
            for (int i = 0; i < 4; i++) {
                int rr = rbase + ((i >= 2) ? 8 : 0);
                int cc = cbase + (i & 1);
                float v = acc[mt][nt][i];
                if (mode == 0) {
                    C[(size_t)rr * N + cc] = v;
                } else {
                    int b = rr >> 11, t = rr & 2047;
                    int which = cc >> 10, rem = cc & 1023;
                    int h = rem >> 6, dd = rem & 63;
                    float* dst = (which == 0) ? g_q : ((which == 1) ? g_k : g_v);
                    dst[(((size_t)(b * HEADS + h)) * SEQT + t) * DH + dd] = v;
                }
            }
        }
    }
}

// ---------------------------------------------------------------------------
// Flash attention v2. Grid (bh=64, qt=8). Block = 256 threads, 8 warps, each
// warp owns 32 query rows (mt=2) of a 256-query tile. K/V stream in 64-key
// tiles, double-buffered with register-staged prefetch. P never hits smem:
// the S C-fragment is shuffled directly into the PV A-fragment.
//   Qs stride 68 (4r+k), Ks stride 68 (4r+k), Vs stride 72 (8k+c).
// ---------------------------------------------------------------------------
#define QSTR 68
#define KST  68
#define VST  72
#define Q_SM   (256 * QSTR)
#define K_SM   (64 * KST)
#define V_SM   (64 * VST)
#define FL_SMEM ((Q_SM + 2 * K_SM + 2 * V_SM) * 4)   // 141,312 B

__global__ __launch_bounds__(256) void flash_attn() {
    extern __shared__ float sm[];
    float* Qs = sm;
    float* Ks = sm + Q_SM;             // [2][64*KST]
    float* Vs = sm + Q_SM + 2 * K_SM;  // [2][64*VST]

    const int bh = blockIdx.x, qt = blockIdx.y;
    const int tid = threadIdx.x, lane = tid & 31, w = tid >> 5;

    const float* Qg = g_q + ((size_t)bh * SEQT + qt * 256) * DH;
    const float* Kg = g_k + (size_t)bh * SEQT * DH;
    const float* Vg = g_v + (size_t)bh * SEQT * DH;

    const int lrow = tid >> 4;          // 0..15
    const int lcol = (tid & 15) * 4;    // 0..60

    // stage Q tile (256x64) with RNA convert
#pragma unroll
    for (int p = 0; p < 16; p++) {
        int r = p * 16 + lrow;
        float4 v = *(const float4*)(Qg + (size_t)r * DH + lcol);
        *(float4*)&Qs[r * QSTR + lcol] = tf32r4(v);
    }

    // stage K/V tile 0
    {
#pragma unroll
        for (int p = 0; p < 4; p++) {
            int r = p * 16 + lrow;
            float4 kv = *(const float4*)(Kg + (size_t)r * DH + lcol);
            float4 vv = *(const float4*)(Vg + (size_t)r * DH + lcol);
            *(float4*)&Ks[r * KST + lcol] = tf32r4(kv);
            *(float4*)&Vs[r * VST + lcol] = tf32r4(vv);
        }
    }
    __syncthreads();

    float m[2][2], l[2][2];
#pragma unroll
    for (int mt = 0; mt < 2; mt++) { m[mt][0] = m[mt][1] = -1e30f; l[mt][0] = l[mt][1] = 0.f; }
    float o[2][8][4];
#pragma unroll
    for (int mt = 0; mt < 2; mt++)
#pragma unroll
        for (int nt = 0; nt < 8; nt++)
#pragma unroll
            for (int i = 0; i < 4; i++) o[mt][nt][i] = 0.f;

    const float SCALE = 0.03125f;  // 1024^-0.5 (full model dim per reference)
    const int src0 = (lane & ~3) | ((lane & 3) >> 1);
    const int src1 = src0 + 2;
    const bool odd = lane & 1;

    for (int j = 0; j < 32; j++) {
        const int cur = j & 1;
        const float* Kc = Ks + cur * K_SM;
        const float* Vc = Vs + cur * V_SM;
        const bool pf = (j + 1 < 32);

        float4 rK[4], rV[4];
        if (pf) {
#pragma unroll
            for (int p = 0; p < 4; p++) {
                size_t off = (size_t)((j + 1) * 64 + p * 16 + lrow) * DH + lcol;
                rK[p] = *(const float4*)(Kg + off);
                rV[p] = *(const float4*)(Vg + off);
            }
        }

        // ---- S = Q @ K^T ----
        float s[2][8][4];
#pragma unroll
        for (int mt = 0; mt < 2; mt++)
#pragma unroll
            for (int nt = 0; nt < 8; nt++)
#pragma unroll
                for (int i = 0; i < 4; i++) s[mt][nt][i] = 0.f;

#pragma unroll
        for (int kc = 0; kc < 8; kc++) {
            const int kd = kc * 8 + (lane & 3);
            unsigned aQ[2][4];
#pragma unroll
            for (int mt = 0; mt < 2; mt++) {
                int r = w * 32 + mt * 16 + (lane >> 2);
                aQ[mt][0] = fb(Qs[r * QSTR + kd]);
                aQ[mt][1] = fb(Qs[(r + 8) * QSTR + kd]);
                aQ[mt][2] = fb(Qs[r * QSTR + kd + 4]);
                aQ[mt][3] = fb(Qs[(r + 8) * QSTR + kd + 4]);
            }
#pragma unroll
            for (int nt = 0; nt < 8; nt++) {
                int key = nt * 8 + (lane >> 2);
                unsigned b0 = fb(Kc[key * KST + kd]);
                unsigned b1 = fb(Kc[key * KST + kd + 4]);
                mma_tf32(s[0][nt], aQ[0], b0, b1);
                mma_tf32(s[1][nt], aQ[1], b0, b1);
            }
        }

        // ---- online softmax (4 row-sets: mt x {row, row+8}) ----
        float mx[2][2] = {{m[0][0], m[0][1]}, {m[1][0], m[1][1]}};
#pragma unroll
        for (int mt = 0; mt < 2; mt++)
#pragma unroll
            for (int nt = 0; nt < 8; nt++) {
                s[mt][nt][0] *= SCALE; s[mt][nt][1] *= SCALE;
                s[mt][nt][2] *= SCALE; s[mt][nt][3] *= SCALE;
                mx[mt][0] = fmaxf(mx[mt][0], fmaxf(s[mt][nt][0], s[mt][nt][1]));
                mx[mt][1] = fmaxf(mx[mt][1], fmaxf(s[mt][nt][2], s[mt][nt][3]));
            }
#pragma unroll
        for (int mt = 0; mt < 2; mt++)
#pragma unroll
            for (int hh = 0; hh < 2; hh++) {
                mx[mt][hh] = fmaxf(mx[mt][hh], __shfl_xor_sync(0xffffffffu, mx[mt][hh], 1));
                mx[mt][hh] = fmaxf(mx[mt][hh], __shfl_xor_sync(0xffffffffu, mx[mt][hh], 2));
            }
        float alpha[2][2], sum[2][2];
#pragma unroll
        for (int mt = 0; mt < 2; mt++)
#pragma unroll
            for (int hh = 0; hh < 2; hh++) {
                alpha[mt][hh] = __expf(m[mt][hh] - mx[mt][hh]);
                m[mt][hh] = mx[mt][hh];
                sum[mt][hh] = 0.f;
            }
#pragma unroll
        for (int mt = 0; mt < 2; mt++)
#pragma unroll
            for (int nt = 0; nt < 8; nt++) {
                float p0 = __expf(s[mt][nt][0] - mx[mt][0]);
                float p1 = __expf(s[mt][nt][1] - mx[mt][0]);
                float p2 = __expf(s[mt][nt][2] - mx[mt][1]);
                float p3 = __expf(s[mt][nt][3] - mx[mt][1]);
                sum[mt][0] += p0 + p1;
                sum[mt][1] += p2 + p3;
                s[mt][nt][0] = p0; s[mt][nt][1] = p1;
                s[mt][nt][2] = p2; s[mt][nt][3] = p3;
                o[mt][nt][0] *= alpha[mt][0]; o[mt][nt][1] *= alpha[mt][0];
                o[mt][nt][2] *= alpha[mt][1]; o[mt][nt][3] *= alpha[mt][1];
            }
#pragma unroll
        for (int mt = 0; mt < 2; mt++)
#pragma unroll
            for (int hh = 0; hh < 2; hh++) {
                sum[mt][hh] += __shfl_xor_sync(0xffffffffu, sum[mt][hh], 1);
                sum[mt][hh] += __shfl_xor_sync(0xffffffffu, sum[mt][hh], 2);
                l[mt][hh] = l[mt][hh] * alpha[mt][hh] + sum[mt][hh];
            }

        // stage next K/V into the other buffer (latency already covered by S)
        if (pf) {
#pragma unroll
            for (int p = 0; p < 4; p++) {
                int r = p * 16 + lrow;
                *(float4*)&Ks[(cur ^ 1) * K_SM + r * KST + lcol] = tf32r4(rK[p]);
                *(float4*)&Vs[(cur ^ 1) * V_SM + r * VST + lcol] = tf32r4(rV[p]);
            }
        }

        // ---- O += P @ V ;  P A-frag built from S C-frag via shuffles ----
#pragma unroll
        for (int kc = 0; kc < 8; kc++) {
            unsigned aP[2][4];
#pragma unroll
            for (int mt = 0; mt < 2; mt++) {
                float c0 = s[mt][kc][0], c1 = s[mt][kc][1];
                float c2 = s[mt][kc][2], c3 = s[mt][kc][3];
                float t00 = __shfl_sync(0xffffffffu, c0, src0);
                float t01 = __shfl_sync(0xffffffffu, c1, src0);
                float t10 = __shfl_sync(0xffffffffu, c2, src0);
                float t11 = __shfl_sync(0xffffffffu, c3, src0);
                float u00 = __shfl_sync(0xffffffffu, c0, src1);
                float u01 = __shfl_sync(0xffffffffu, c1, src1);
                float u10 = __shfl_sync(0xffffffffu, c2, src1);
                float u11 = __shfl_sync(0xffffffffu, c3, src1);
                aP[mt][0] = fb(tf32r(odd ? t01 : t00));
                aP[mt][1] = fb(tf32r(odd ? t11 : t10));
                aP[mt][2] = fb(tf32r(odd ? u01 : u00));
                aP[mt][3] = fb(tf32r(odd ? u11 : u10));
            }
            const int kk = kc * 8 + (lane & 3);
#pragma unroll
            for (int nt = 0; nt < 8; nt++) {
                int cc = nt * 8 + (lane >> 2);
                unsigned b0 = fb(Vc[kk * VST + cc]);
                unsigned b1 = fb(Vc[(kk + 4) * VST + cc]);
                mma_tf32(o[0][nt], aP[0], b0, b1);
                mma_tf32(o[1][nt], aP[1], b0, b1);
            }
        }
        __syncthreads();
    }

    // ---- epilogue: normalize, write g_o [8192][1024] ----
    const int b = bh >> 4, hd = bh & 15;
    float inv[2][2];
#pragma unroll
    for (int mt = 0; mt < 2; mt++) {
        inv[mt][0] = 1.f / l[mt][0];
        inv[mt][1] = 1.f / l[mt][1];
    }
#pragma unroll
    for (int mt = 0; mt < 2; mt++) {
        size_t row0 = (size_t)b * SEQT + qt * 256 + w * 32 + mt * 16 + (lane >> 2);
#pragma unroll
        for (int nt = 0; nt < 8; nt++) {
            int cc = hd * DH + nt * 8 + 2 * (lane & 3);
            g_o[row0 * DMODEL + cc]           = o[mt][nt][0] * inv[mt][0];
            g_o[row0 * DMODEL + cc + 1]       = o[mt][nt][1] * inv[mt][0];
            g_o[(row0 + 8) * DMODEL + cc]     = o[mt][nt][2] * inv[mt][1];
            g_o[(row0 + 8) * DMODEL + cc + 1] = o[mt][nt][3] * inv[mt][1];
        }
    }
}

// ---------------------------------------------------------------------------
extern "C" void kernel_launch(void* const* d_in, const int* in_sizes, int n_in,
                              void* d_out, int out_size) {
    const float* x     = (const float*)d_in[0];  // [4,2048,1024]
    const float* w_qkv = (const float*)d_in[1];  // [1024,3072]
    const float* w_out = (const float*)d_in[2];  // [1024,1024]
    float* out = (float*)d_out;                  // [4,2048,1024]

    gemm_tf32<<<dim3(3 * DMODEL / BN, MROWS / BM), 128>>>(
        x, w_qkv, nullptr, MROWS, 3 * DMODEL, DMODEL, 1);

    cudaFuncSetAttribute(flash_attn, cudaFuncAttributeMaxDynamicSharedMemorySize,
                         FL_SMEM);
    flash_attn<<<dim3(BHEADS, SEQT / 256), 256, FL_SMEM>>>();

    gemm_tf32<<<dim3(DMODEL / BN, MROWS / BM), 128>>>(
        nullptr, w_out, out, MROWS, DMODEL, DMODEL, 0);
}

// round 8
// speedup vs baseline: 1.3456x; 1.1625x over previous
#include <cuda_runtime.h>
#include <cstdint>

#define HEADS   16
#define DH      64
#define SEQT    2048
#define BATCH   4
#define DMODEL  1024
#define KDIM    1024
#define BHEADS  (BATCH * HEADS)   // 64
#define MROWS   (BATCH * SEQT)    // 8192

__device__ float g_q[(size_t)BHEADS * SEQT * DH];
__device__ float g_k[(size_t)BHEADS * SEQT * DH];
__device__ float g_v[(size_t)BHEADS * SEQT * DH];
__device__ float g_o[(size_t)MROWS * DMODEL];
__device__ float g_xr[(size_t)MROWS * DMODEL];
__device__ float g_wq[(size_t)3 * DMODEL * DMODEL];  // rounded w_qkv [1024][3072]
__device__ float g_wo[(size_t)DMODEL * DMODEL];      // rounded w_out [1024][1024]

// ---------------- helpers ----------------
__device__ __forceinline__ float tf32r(float f) {
    unsigned u;
    asm("cvt.rna.tf32.f32 %0, %1;" : "=r"(u) : "f"(f));
    return __uint_as_float(u);
}
__device__ __forceinline__ float4 tf32r4(float4 v) {
    return make_float4(tf32r(v.x), tf32r(v.y), tf32r(v.z), tf32r(v.w));
}
__device__ __forceinline__ unsigned fb(float f) { return __float_as_uint(f); }

__device__ __forceinline__ uint32_t smem_u32(const void* p) {
    uint32_t a;
    asm("{ .reg .u64 t; cvta.to.shared.u64 t, %1; cvt.u32.u64 %0, t; }"
        : "=r"(a) : "l"(p));
    return a;
}

#define CP16(dst, src) \
    asm volatile("cp.async.cg.shared.global [%0], [%1], 16;" \
                 :: "r"(dst), "l"(src) : "memory")
#define CP_COMMIT() asm volatile("cp.async.commit_group;" ::: "memory")
#define CP_WAIT1()  asm volatile("cp.async.wait_group 1;" ::: "memory")
#define CP_WAIT0()  asm volatile("cp.async.wait_group 0;" ::: "memory")

__device__ __forceinline__ void mma_tf32(float* c, const unsigned* a,
                                         unsigned b0, unsigned b1) {
    asm volatile(
        "mma.sync.aligned.m16n8k8.row.col.f32.tf32.tf32.f32 "
        "{%0,%1,%2,%3},{%4,%5,%6,%7},{%8,%9},{%0,%1,%2,%3};\n"
        : "+f"(c[0]), "+f"(c[1]), "+f"(c[2]), "+f"(c[3])
        : "r"(a[0]), "r"(a[1]), "r"(a[2]), "r"(a[3]), "r"(b0), "r"(b1));
}

// ---------------- prep: RNA tf32 rounding ----------------
__global__ void round_x(const float4* __restrict__ src) {
    int i = blockIdx.x * blockDim.x + threadIdx.x;
    ((float4*)g_xr)[i] = tf32r4(src[i]);
}
__global__ void round_wq(const float4* __restrict__ src) {
    int i = blockIdx.x * blockDim.x + threadIdx.x;
    ((float4*)g_wq)[i] = tf32r4(src[i]);
}
__global__ void round_wo(const float4* __restrict__ src) {
    int i = blockIdx.x * blockDim.x + threadIdx.x;
    ((float4*)g_wo)[i] = tf32r4(src[i]);
}

// ---------------------------------------------------------------------------
// GEMM: C[M][N] = A[M][1024] @ B[1024][N], tf32 mma.sync.
// BM=128 BN=128 BK=32, 128 threads (4 warps 2x2), warp tile 64x64.
// 3-stage cp.async ring, one __syncthreads per K-slice. Inputs pre-rounded.
// ---------------------------------------------------------------------------
#define BK        32
#define ASTR      36
#define BSTR      136
#define AS_FLOATS (128 * ASTR)              // 4608
#define BS_FLOATS (BK * BSTR)               // 4352
#define STG_FL    (AS_FLOATS + BS_FLOATS)   // 8960
#define G_SMEM    (3 * STG_FL * 4)          // 107,520 B -> 2 CTAs/SM

__device__ __forceinline__ void g_load_slice(uint32_t sbase, const float* __restrict__ A,
                                             const float* __restrict__ B, int N,
                                             int bm, int bn, int kt, int tid) {
    const uint32_t sa = sbase;
    const uint32_t sb = sbase + AS_FLOATS * 4;
    const float* arow = A + (size_t)bm * 128 * KDIM + kt * 32;
    const float* brow = B + (size_t)kt * 32 * N + bn * 128;
#pragma unroll
    for (int p = 0; p < 8; p++) {           // A: 128x32 = 1024 16B chunks
        int idx = tid + 128 * p;
        int r = idx >> 3, k4 = idx & 7;
        CP16(sa + r * (ASTR * 4) + k4 * 16, arow + (size_t)r * KDIM + k4 * 4);
    }
#pragma unroll
    for (int p = 0; p < 8; p++) {           // B: 32x128 = 1024 16B chunks
        int idx = tid + 128 * p;
        int kk = idx >> 5, c = idx & 31;
        CP16(sb + kk * (BSTR * 4) + c * 16, brow + (size_t)kk * N + c * 4);
    }
}

__global__ __launch_bounds__(128) void gemm_tf32(float* __restrict__ C, int N,
                                                 int mode) {
    extern __shared__ float sm[];
    const uint32_t sm0 = smem_u32(sm);

    const int tid = threadIdx.x, lane = tid & 31, wid = tid >> 5;
    const int wm = wid >> 1, wn = wid & 1;
    const int bn = blockIdx.x, bm = blockIdx.y;

    const float* A = mode ? g_xr : g_o;
    const float* B = mode ? g_wq : g_wo;

    float acc[4][8][4];
#pragma unroll
    for (int mt = 0; mt < 4; mt++)
#pragma unroll
        for (int nt = 0; nt < 8; nt++)
#pragma unroll
            for (int i = 0; i < 4; i++) acc[mt][nt][i] = 0.f;

    g_load_slice(sm0 + 0 * STG_FL * 4, A, B, N, bm, bn, 0, tid); CP_COMMIT();
    g_load_slice(sm0 + 1 * STG_FL * 4, A, B, N, bm, bn, 1, tid); CP_COMMIT();

    const int NSL = KDIM / BK;   // 32
    for (int j = 0; j < NSL; j++) {
        if (j < NSL - 1) { CP_WAIT1(); } else { CP_WAIT0(); }
        __syncthreads();
        if (j + 2 < NSL) {
            g_load_slice(sm0 + ((j + 2) % 3) * STG_FL * 4, A, B, N, bm, bn, j + 2, tid);
            CP_COMMIT();
        }

        const float* As_ = sm + (j % 3) * STG_FL;
        const float* Bs_ = As_ + AS_FLOATS;
#pragma unroll
        for (int kc = 0; kc < 4; kc++) {
            const int kk = kc * 8 + (lane & 3);
            unsigned a[4][4];
#pragma unroll
            for (int mt = 0; mt < 4; mt++) {
                int r = wm * 64 + mt * 16 + (lane >> 2);
                a[mt][0] = fb(As_[r * ASTR + kk]);
                a[mt][1] = fb(As_[(r + 8) * ASTR + kk]);
                a[mt][2] = fb(As_[r * ASTR + kk + 4]);
                a[mt][3] = fb(As_[(r + 8) * ASTR + kk + 4]);
            }
            unsigned b[8][2];
#pragma unroll
            for (int nt = 0; nt < 8; nt++) {
                int cc = wn * 64 + nt * 8 + (lane >> 2);
                b[nt][0] = fb(Bs_[kk * BSTR + cc]);
                b[nt][1] = fb(Bs_[(kk + 4) * BSTR + cc]);
            }
#pragma unroll
            for (int mt = 0; mt < 4; mt++)
#pragma unroll
                for (int nt = 0; nt < 8; nt++)
                    mma_tf32(acc[mt][nt], a[mt], b[nt][0], b[nt][1]);
        }
    }

    // epilogue
#pragma unroll
    for (int mt = 0; mt < 4; mt++) {
#pragma unroll
        for (int nt = 0; nt < 8; nt++) {
            int rbase = bm * 128 + wm * 64 + mt * 16 + (lane >> 2);
            int cbase = bn * 128 + wn * 64 + nt * 8 + 2 * (lane & 3);
#pragma unroll
            for (int i = 0; i < 4; i++) {
                int rr = rbase + ((i >= 2) ? 8 : 0);
                int cc = cbase + (i & 1);
                float v = acc[mt][nt][i];
                if (mode == 0) {
                    C[(size_t)rr * N + cc] = v;
                } else {
                    int b = rr >> 11, t = rr & 2047;
                    int which = cc >> 10, rem = cc & 1023;
                    int h = rem >> 6, dd = rem & 63;
                    float* dst = (which == 0) ? g_q : ((which == 1) ? g_k : g_v);
                    dst[(((size_t)(b * HEADS + h)) * SEQT + t) * DH + dd] = tf32r(v);
                }
            }
        }
    }
}

// ---------------------------------------------------------------------------
// Flash attention v3 (fixed): sum quad-reduction restored before l update.
// ---------------------------------------------------------------------------
#define KST 68
#define VST 72
#define QPK_FL (8 * 8 * 2 * 32 * 4)    // 16384 floats (64 KB)
#define K_FL   (64 * KST)              // 4352
#define V_FL   (64 * VST)              // 4608
#define FL_SMEM ((QPK_FL + 3 * K_FL + 3 * V_FL) * 4)   // 173,056 B

__device__ __forceinline__ void fl_issue_kv(uint32_t kbase, uint32_t vbase,
                                            const float* __restrict__ Kg,
                                            const float* __restrict__ Vg,
                                            int tile, int tid) {
    const float* kp = Kg + (size_t)tile * 64 * DH;
    const float* vp = Vg + (size_t)tile * 64 * DH;
#pragma unroll
    for (int p = 0; p < 4; p++) {          // 64x64 = 1024 chunks / 256 thr
        int idx = tid + 256 * p;
        int row = idx >> 4, c16 = idx & 15;
        CP16(kbase + row * (KST * 4) + c16 * 16, kp + (size_t)row * DH + c16 * 4);
        CP16(vbase + row * (VST * 4) + c16 * 16, vp + (size_t)row * DH + c16 * 4);
    }
}

__global__ __launch_bounds__(256) void flash_attn() {
    extern __shared__ float sm[];
    float* Qs = sm;                         // packed fragments
    float* Ks = sm + QPK_FL;                // 3 stages
    float* Vs = sm + QPK_FL + 3 * K_FL;     // 3 stages
    const uint32_t sm0 = smem_u32(sm);
    const uint32_t kbase0 = sm0 + QPK_FL * 4;
    const uint32_t vbase0 = sm0 + (QPK_FL + 3 * K_FL) * 4;

    const int bh = blockIdx.x, qt = blockIdx.y;
    const int tid = threadIdx.x, lane = tid & 31, w = tid >> 5;

    const float* Qg = g_q + ((size_t)bh * SEQT + qt * 256) * DH;
    const float* Kg = g_k + (size_t)bh * SEQT * DH;
    const float* Vg = g_v + (size_t)bh * SEQT * DH;

    // ---- stage Q into fragment-packed layout (one row per thread) ----
    {
        const int r = tid;
        const float4* qrow = (const float4*)(Qg + (size_t)r * DH);
        const int wq = r >> 5, rr = r & 31, mt = rr >> 4, r16 = rr & 15;
        const int lane_hi = (r16 & 7) << 2;
        const int j0 = r16 >> 3;
#pragma unroll
        for (int p = 0; p < 16; p++) {
            float4 v = qrow[p];
            int cbase = p * 4;
#pragma unroll
            for (int q = 0; q < 4; q++) {
                int c = cbase + q;
                int kc = c >> 3;
                int jj = j0 | (((c >> 2) & 1) << 1);
                int ln = lane_hi | (c & 3);
                float val = (q == 0) ? v.x : (q == 1) ? v.y : (q == 2) ? v.z : v.w;
                Qs[((((wq << 3) + kc) << 1) + mt) * 128 + ln * 4 + jj] = val;
            }
        }
    }

    fl_issue_kv(kbase0, vbase0, Kg, Vg, 0, tid); CP_COMMIT();
    fl_issue_kv(kbase0 + K_FL * 4, vbase0 + V_FL * 4, Kg, Vg, 1, tid); CP_COMMIT();
    __syncthreads();   // Q visible

    float m[2][2], l[2][2];
#pragma unroll
    for (int mt = 0; mt < 2; mt++) { m[mt][0] = m[mt][1] = -1e30f; l[mt][0] = l[mt][1] = 0.f; }
    float o[2][8][4];
#pragma unroll
    for (int mt = 0; mt < 2; mt++)
#pragma unroll
        for (int nt = 0; nt < 8; nt++)
#pragma unroll
            for (int i = 0; i < 4; i++) o[mt][nt][i] = 0.f;

    const float SCALE2 = 0.03125f * 1.4426950408889634f;  // scale * log2(e)
    const int src0 = (lane & ~3) | ((lane & 3) >> 1);
    const int src1 = src0 + 2;
    const bool odd = lane & 1;

    for (int j = 0; j < 32; j++) {
        if (j < 31) { CP_WAIT1(); } else { CP_WAIT0(); }
        __syncthreads();
        if (j + 2 < 32) {
            int sp = (j + 2) % 3;
            fl_issue_kv(kbase0 + sp * K_FL * 4, vbase0 + sp * V_FL * 4, Kg, Vg,
                        j + 2, tid);
            CP_COMMIT();
        }
        const float* Kc = Ks + (j % 3) * K_FL;
        const float* Vc = Vs + (j % 3) * V_FL;

        // ---- S = Q @ K^T ----
        float s[2][8][4];
#pragma unroll
        for (int mt = 0; mt < 2; mt++)
#pragma unroll
            for (int nt = 0; nt < 8; nt++)
#pragma unroll
                for (int i = 0; i < 4; i++) s[mt][nt][i] = 0.f;

#pragma unroll
        for (int kc = 0; kc < 8; kc++) {
            const float4 q0 = *(const float4*)&Qs[((((w << 3) + kc) << 1) + 0) * 128 + lane * 4];
            const float4 q1 = *(const float4*)&Qs[((((w << 3) + kc) << 1) + 1) * 128 + lane * 4];
            unsigned aQ0[4] = {fb(q0.x), fb(q0.y), fb(q0.z), fb(q0.w)};
            unsigned aQ1[4] = {fb(q1.x), fb(q1.y), fb(q1.z), fb(q1.w)};
            const int kd = kc * 8 + (lane & 3);
#pragma unroll
            for (int nt = 0; nt < 8; nt++) {
                int key = nt * 8 + (lane >> 2);
                unsigned b0 = fb(Kc[key * KST + kd]);
                unsigned b1 = fb(Kc[key * KST + kd + 4]);
                mma_tf32(s[0][nt], aQ0, b0, b1);
                mma_tf32(s[1][nt], aQ1, b0, b1);
            }
        }

        // ---- max (exp2 domain) ----
        float mx[2][2] = {{m[0][0], m[0][1]}, {m[1][0], m[1][1]}};
#pragma unroll
        for (int mt = 0; mt < 2; mt++)
#pragma unroll
            for (int nt = 0; nt < 8; nt++) {
                s[mt][nt][0] *= SCALE2; s[mt][nt][1] *= SCALE2;
                s[mt][nt][2] *= SCALE2; s[mt][nt][3] *= SCALE2;
                mx[mt][0] = fmaxf(mx[mt][0], fmaxf(s[mt][nt][0], s[mt][nt][1]));
                mx[mt][1] = fmaxf(mx[mt][1], fmaxf(s[mt][nt][2], s[mt][nt][3]));
            }
#pragma unroll
        for (int mt = 0; mt < 2; mt++)
#pragma unroll
            for (int hh = 0; hh < 2; hh++) {
                mx[mt][hh] = fmaxf(mx[mt][hh], __shfl_xor_sync(0xffffffffu, mx[mt][hh], 1));
                mx[mt][hh] = fmaxf(mx[mt][hh], __shfl_xor_sync(0xffffffffu, mx[mt][hh], 2));
            }
        float alpha[2][2];
#pragma unroll
        for (int mt = 0; mt < 2; mt++)
#pragma unroll
            for (int hh = 0; hh < 2; hh++) {
                alpha[mt][hh] = exp2f(m[mt][hh] - mx[mt][hh]);
                m[mt][hh] = mx[mt][hh];
            }
#pragma unroll
        for (int mt = 0; mt < 2; mt++)
#pragma unroll
            for (int nt = 0; nt < 8; nt++) {
                o[mt][nt][0] *= alpha[mt][0]; o[mt][nt][1] *= alpha[mt][0];
                o[mt][nt][2] *= alpha[mt][1]; o[mt][nt][3] *= alpha[mt][1];
            }

        // ---- fused exp + transpose + PV mma, per 8-key group ----
        float sum[2][2] = {{0.f, 0.f}, {0.f, 0.f}};
#pragma unroll
        for (int kc = 0; kc < 8; kc++) {
            unsigned aP[2][4];
#pragma unroll
            for (int mt = 0; mt < 2; mt++) {
                float p0 = exp2f(s[mt][kc][0] - mx[mt][0]);
                float p1 = exp2f(s[mt][kc][1] - mx[mt][0]);
                float p2 = exp2f(s[mt][kc][2] - mx[mt][1]);
                float p3 = exp2f(s[mt][kc][3] - mx[mt][1]);
                sum[mt][0] += p0 + p1;
                sum[mt][1] += p2 + p3;
                float t00 = __shfl_sync(0xffffffffu, p0, src0);
                float t01 = __shfl_sync(0xffffffffu, p1, src0);
                float t10 = __shfl_sync(0xffffffffu, p2, src0);
                float t11 = __shfl_sync(0xffffffffu, p3, src0);
                float u00 = __shfl_sync(0xffffffffu, p0, src1);
                float u01 = __shfl_sync(0xffffffffu, p1, src1);
                float u10 = __shfl_sync(0xffffffffu, p2, src1);
                float u11 = __shfl_sync(0xffffffffu, p3, src1);
                aP[mt][0] = fb(odd ? t01 : t00);
                aP[mt][1] = fb(odd ? t11 : t10);
                aP[mt][2] = fb(odd ? u01 : u00);
                aP[mt][3] = fb(odd ? u11 : u10);
            }
            const int kk = kc * 8 + (lane & 3);
#pragma unroll
            for (int nt = 0; nt < 8; nt++) {
                int cc = nt * 8 + (lane >> 2);
                unsigned b0 = fb(Vc[kk * VST + cc]);
                unsigned b1 = fb(Vc[(kk + 4) * VST + cc]);
                mma_tf32(o[0][nt], aP[0], b0, b1);
                mma_tf32(o[1][nt], aP[1], b0, b1);
            }
        }
        // FIX (R8): quad-reduce the partial row sums before folding into l.
#pragma unroll
        for (int mt = 0; mt < 2; mt++)
#pragma unroll
            for (int hh = 0; hh < 2; hh++) {
                sum[mt][hh] += __shfl_xor_sync(0xffffffffu, sum[mt][hh], 1);
                sum[mt][hh] += __shfl_xor_sync(0xffffffffu, sum[mt][hh], 2);
                l[mt][hh] = l[mt][hh] * alpha[mt][hh] + sum[mt][hh];
            }
    }

    // ---- epilogue: normalize, round, write g_o ----
    const int b = bh >> 4, hd = bh & 15;
    float inv[2][2];
#pragma unroll
    for (int mt = 0; mt < 2; mt++) {
        inv[mt][0] = 1.f / l[mt][0];
        inv[mt][1] = 1.f / l[mt][1];
    }
#pragma unroll
    for (int mt = 0; mt < 2; mt++) {
        size_t row0 = (size_t)b * SEQT + qt * 256 + w * 32 + mt * 16 + (lane >> 2);
#pragma unroll
        for (int nt = 0; nt < 8; nt++) {
            int cc = hd * DH + nt * 8 + 2 * (lane & 3);
            g_o[row0 * DMODEL + cc]           = tf32r(o[mt][nt][0] * inv[mt][0]);
            g_o[row0 * DMODEL + cc + 1]       = tf32r(o[mt][nt][1] * inv[mt][0]);
            g_o[(row0 + 8) * DMODEL + cc]     = tf32r(o[mt][nt][2] * inv[mt][1]);
            g_o[(row0 + 8) * DMODEL + cc + 1] = tf32r(o[mt][nt][3] * inv[mt][1]);
        }
    }
}

// ---------------------------------------------------------------------------
extern "C" void kernel_launch(void* const* d_in, const int* in_sizes, int n_in,
                              void* d_out, int out_size) {
    const float* x     = (const float*)d_in[0];  // [4,2048,1024]
    const float* w_qkv = (const float*)d_in[1];  // [1024,3072]
    const float* w_out = (const float*)d_in[2];  // [1024,1024]
    float* out = (float*)d_out;                  // [4,2048,1024]

    round_x <<<MROWS * DMODEL / 4 / 256, 256>>>((const float4*)x);
    round_wq<<<3 * DMODEL * DMODEL / 4 / 256, 256>>>((const float4*)w_qkv);
    round_wo<<<DMODEL * DMODEL / 4 / 256, 256>>>((const float4*)w_out);

    cudaFuncSetAttribute(gemm_tf32, cudaFuncAttributeMaxDynamicSharedMemorySize,
                         G_SMEM);
    cudaFuncSetAttribute(flash_attn, cudaFuncAttributeMaxDynamicSharedMemorySize,
                         FL_SMEM);

    // K1: QKV projection, scatter + round epilogue
    gemm_tf32<<<dim3(3 * DMODEL / 128, MROWS / 128), 128, G_SMEM>>>(nullptr,
                                                                    3 * DMODEL, 1);
    // K2: flash attention
    flash_attn<<<dim3(BHEADS, SEQT / 256), 256, FL_SMEM>>>();

    // K3: output projection
    gemm_tf32<<<dim3(DMODEL / 128, MROWS / 128), 128, G_SMEM>>>(out, DMODEL, 0);
}

// round 10
// speedup vs baseline: 1.3944x; 1.0362x over previous
#include <cuda_runtime.h>
#include <cstdint>

#define HEADS   16
#define DH      64
#define SEQT    2048
#define BATCH   4
#define DMODEL  1024
#define KDIM    1024
#define BHEADS  (BATCH * HEADS)   // 64
#define MROWS   (BATCH * SEQT)    // 8192

__device__ float g_q[(size_t)BHEADS * SEQT * DH];
__device__ float g_k[(size_t)BHEADS * SEQT * DH];
__device__ float g_v[(size_t)BHEADS * SEQT * DH];
__device__ float g_o[(size_t)MROWS * DMODEL];
__device__ float g_xr[(size_t)MROWS * DMODEL];
__device__ float g_wq[(size_t)3 * DMODEL * DMODEL];  // rounded w_qkv [1024][3072]
__device__ float g_wo[(size_t)DMODEL * DMODEL];      // rounded w_out [1024][1024]

// ---------------- helpers ----------------
__device__ __forceinline__ float tf32r(float f) {
    unsigned u;
    asm("cvt.rna.tf32.f32 %0, %1;" : "=r"(u) : "f"(f));
    return __uint_as_float(u);
}
__device__ __forceinline__ float4 tf32r4(float4 v) {
    return make_float4(tf32r(v.x), tf32r(v.y), tf32r(v.z), tf32r(v.w));
}
__device__ __forceinline__ unsigned fb(float f) { return __float_as_uint(f); }

__device__ __forceinline__ uint32_t smem_u32(const void* p) {
    uint32_t a;
    asm("{ .reg .u64 t; cvta.to.shared.u64 t, %1; cvt.u32.u64 %0, t; }"
        : "=r"(a) : "l"(p));
    return a;
}

#define CP16(dst, src) \
    asm volatile("cp.async.cg.shared.global [%0], [%1], 16;" \
                 :: "r"(dst), "l"(src) : "memory")
#define CP_COMMIT() asm volatile("cp.async.commit_group;" ::: "memory")
#define CP_WAIT0()  asm volatile("cp.async.wait_group 0;" ::: "memory")

__device__ __forceinline__ void mma_tf32(float* c, const unsigned* a,
                                         unsigned b0, unsigned b1) {
    asm volatile(
        "mma.sync.aligned.m16n8k8.row.col.f32.tf32.tf32.f32 "
        "{%0,%1,%2,%3},{%4,%5,%6,%7},{%8,%9},{%0,%1,%2,%3};\n"
        : "+f"(c[0]), "+f"(c[1]), "+f"(c[2]), "+f"(c[3])
        : "r"(a[0]), "r"(a[1]), "r"(a[2]), "r"(a[3]), "r"(b0), "r"(b1));
}

// ---------------- prep: RNA tf32 rounding ----------------
__global__ void round_x(const float4* __restrict__ src) {
    int i = blockIdx.x * blockDim.x + threadIdx.x;
    ((float4*)g_xr)[i] = tf32r4(src[i]);
}
__global__ void round_wq(const float4* __restrict__ src) {
    int i = blockIdx.x * blockDim.x + threadIdx.x;
    ((float4*)g_wq)[i] = tf32r4(src[i]);
}
__global__ void round_wo(const float4* __restrict__ src) {
    int i = blockIdx.x * blockDim.x + threadIdx.x;
    ((float4*)g_wo)[i] = tf32r4(src[i]);
}

// ---------------------------------------------------------------------------
// GEMM: C[M][N] = A[M][1024] @ B[1024][N], tf32 mma.sync.
// BM=128 BN=128 BK=32, 128 threads (4 warps 2x2), warp tile 64x64.
// 2-stage cp.async ring (71.7KB) + launch_bounds(128,3) -> 3 CTAs/SM.
// ---------------------------------------------------------------------------
#define BK        32
#define ASTR      36
#define BSTR      136
#define AS_FLOATS (128 * ASTR)              // 4608
#define BS_FLOATS (BK * BSTR)               // 4352
#define STG_FL    (AS_FLOATS + BS_FLOATS)   // 8960
#define G_SMEM    (2 * STG_FL * 4)          // 71,680 B -> 3 CTAs/SM

__device__ __forceinline__ void g_load_slice(uint32_t sbase, const float* __restrict__ A,
                                             const float* __restrict__ B, int N,
                                             int bm, int bn, int kt, int tid) {
    const uint32_t sa = sbase;
    const uint32_t sb = sbase + AS_FLOATS * 4;
    const float* arow = A + (size_t)bm * 128 * KDIM + kt * 32;
    const float* brow = B + (size_t)kt * 32 * N + bn * 128;
#pragma unroll
    for (int p = 0; p < 8; p++) {           // A: 128x32 = 1024 16B chunks
        int idx = tid + 128 * p;
        int r = idx >> 3, k4 = idx & 7;
        CP16(sa + r * (ASTR * 4) + k4 * 16, arow + (size_t)r * KDIM + k4 * 4);
    }
#pragma unroll
    for (int p = 0; p < 8; p++) {           // B: 32x128 = 1024 16B chunks
        int idx = tid + 128 * p;
        int kk = idx >> 5, c = idx & 31;
        CP16(sb + kk * (BSTR * 4) + c * 16, brow + (size_t)kk * N + c * 4);
    }
}

__global__ __launch_bounds__(128, 3) void gemm_tf32(float* __restrict__ C, int N,
                                                    int mode) {
    extern __shared__ float sm[];
    const uint32_t sm0 = smem_u32(sm);

    const int tid = threadIdx.x, lane = tid & 31, wid = tid >> 5;
    const int wm = wid >> 1, wn = wid & 1;
    const int bn = blockIdx.x, bm = blockIdx.y;

    const float* A = mode ? g_xr : g_o;
    const float* B = mode ? g_wq : g_wo;

    float acc[4][8][4];
#pragma unroll
    for (int mt = 0; mt < 4; mt++)
#pragma unroll
        for (int nt = 0; nt < 8; nt++)
#pragma unroll
            for (int i = 0; i < 4; i++) acc[mt][nt][i] = 0.f;

    g_load_slice(sm0, A, B, N, bm, bn, 0, tid); CP_COMMIT();

    const int NSL = KDIM / BK;   // 32
    for (int j = 0; j < NSL; j++) {
        CP_WAIT0();
        __syncthreads();
        if (j + 1 < NSL) {
            g_load_slice(sm0 + ((j + 1) & 1) * STG_FL * 4, A, B, N, bm, bn, j + 1, tid);
            CP_COMMIT();
        }

        const float* As_ = sm + (j & 1) * STG_FL;
        const float* Bs_ = As_ + AS_FLOATS;
#pragma unroll
        for (int kc = 0; kc < 4; kc++) {
            const int kk = kc * 8 + (lane & 3);
            unsigned a[4][4];
#pragma unroll
            for (int mt = 0; mt < 4; mt++) {
                int r = wm * 64 + mt * 16 + (lane >> 2);
                a[mt][0] = fb(As_[r * ASTR + kk]);
                a[mt][1] = fb(As_[(r + 8) * ASTR + kk]);
                a[mt][2] = fb(As_[r * ASTR + kk + 4]);
                a[mt][3] = fb(As_[(r + 8) * ASTR + kk + 4]);
            }
            unsigned b[8][2];
#pragma unroll
            for (int nt = 0; nt < 8; nt++) {
                int cc = wn * 64 + nt * 8 + (lane >> 2);
                b[nt][0] = fb(Bs_[kk * BSTR + cc]);
                b[nt][1] = fb(Bs_[(kk + 4) * BSTR + cc]);
            }
#pragma unroll
            for (int mt = 0; mt < 4; mt++)
#pragma unroll
                for (int nt = 0; nt < 8; nt++)
                    mma_tf32(acc[mt][nt], a[mt], b[nt][0], b[nt][1]);
        }
    }

    // epilogue
#pragma unroll
    for (int mt = 0; mt < 4; mt++) {
#pragma unroll
        for (int nt = 0; nt < 8; nt++) {
            int rbase = bm * 128 + wm * 64 + mt * 16 + (lane >> 2);
            int cbase = bn * 128 + wn * 64 + nt * 8 + 2 * (lane & 3);
#pragma unroll
            for (int i = 0; i < 4; i++) {
                int rr = rbase + ((i >= 2) ? 8 : 0);
                int cc = cbase + (i & 1);
                float v = acc[mt][nt][i];
                if (mode == 0) {
                    C[(size_t)rr * N + cc] = v;
                } else {
                    int b = rr >> 11, t = rr & 2047;
                    int which = cc >> 10, rem = cc & 1023;
                    int h = rem >> 6, dd = rem & 63;
                    float* dst = (which == 0) ? g_q : ((which == 1) ? g_k : g_v);
                    dst[(((size_t)(b * HEADS + h)) * SEQT + t) * DH + dd] = tf32r(v);
                }
            }
        }
    }
}

// ---------------------------------------------------------------------------
// Flash attention v4. Grid (bh=64, qt=16), 256 threads / 8 warps, warp = 16 q
// rows. Q fragment-packed (32KB); K/V 2-stage cp.async ring (71.7KB);
// total 104.4KB -> 2 CTAs/SM (4 warps/SMSP). exp2-domain softmax fused
// into the PV mma loop.
// ---------------------------------------------------------------------------
#define KST 68
#define VST 72
#define QPK_FL (8 * 8 * 32 * 4)        // 8192 floats (32 KB)
#define K_FL   (64 * KST)              // 4352
#define V_FL   (64 * VST)              // 4608
#define FL_SMEM ((QPK_FL + 2 * (K_FL + V_FL)) * 4)   // 104,448 B

__device__ __forceinline__ void fl_issue_kv(uint32_t kbase, uint32_t vbase,
                                            const float* __restrict__ Kg,
                                            const float* __restrict__ Vg,
                                            int tile, int tid) {
    const float* kp = Kg + (size_t)tile * 64 * DH;
    const float* vp = Vg + (size_t)tile * 64 * DH;
#pragma unroll
    for (int p = 0; p < 4; p++) {          // 64x64 = 1024 chunks / 256 thr
        int idx = tid + 256 * p;
        int row = idx >> 4, c16 = idx & 15;
        CP16(kbase + row * (KST * 4) + c16 * 16, kp + (size_t)row * DH + c16 * 4);
        CP16(vbase + row * (VST * 4) + c16 * 16, vp + (size_t)row * DH + c16 * 4);
    }
}

__global__ __launch_bounds__(256, 2) void flash_attn() {
    extern __shared__ float sm[];
    float* Qs = sm;                         // packed fragments, 8192 floats
    float* Ks = sm + QPK_FL;                // 2 stages
    float* Vs = sm + QPK_FL + 2 * K_FL;     // 2 stages
    const uint32_t sm0 = smem_u32(sm);
    const uint32_t kbase0 = sm0 + QPK_FL * 4;
    const uint32_t vbase0 = sm0 + (QPK_FL + 2 * K_FL) * 4;

    const int bh = blockIdx.x, qt = blockIdx.y;
    const int tid = threadIdx.x, lane = tid & 31, w = tid >> 5;

    const float* Qg = g_q + ((size_t)bh * SEQT + qt * 128) * DH;
    const float* Kg = g_k + (size_t)bh * SEQT * DH;
    const float* Vg = g_v + (size_t)bh * SEQT * DH;

    // ---- stage Q (128x64) into fragment-packed layout: 2 threads per row ----
    {
        const int r = tid >> 1;            // 0..127
        const int half = tid & 1;          // cols [half*32, half*32+32)
        const float4* qrow = (const float4*)(Qg + (size_t)r * DH);
        const int wq = r >> 4, r16 = r & 15;
        const int lane_hi = (r16 & 7) << 2;
        const int j0 = r16 >> 3;
#pragma unroll
        for (int p = 0; p < 8; p++) {
            float4 v = qrow[half * 8 + p];
            int cbase = half * 32 + p * 4;
#pragma unroll
            for (int q = 0; q < 4; q++) {
                int c = cbase + q;
                int kc = c >> 3;
                int jj = j0 | (((c >> 2) & 1) << 1);
                int ln = lane_hi | (c & 3);
                float val = (q == 0) ? v.x : (q == 1) ? v.y : (q == 2) ? v.z : v.w;
                Qs[((wq << 3) + kc) * 128 + ln * 4 + jj] = val;
            }
        }
    }

    fl_issue_kv(kbase0, vbase0, Kg, Vg, 0, tid); CP_COMMIT();

    float m[2] = {-1e30f, -1e30f}, l[2] = {0.f, 0.f};
    float o[8][4];
#pragma unroll
    for (int nt = 0; nt < 8; nt++)
#pragma unroll
        for (int i = 0; i < 4; i++) o[nt][i] = 0.f;

    const float SCALE2 = 0.03125f * 1.4426950408889634f;  // scale * log2(e)
    const int src0 = (lane & ~3) | ((lane & 3) >> 1);
    const int src1 = src0 + 2;
    const bool odd = lane & 1;

    for (int j = 0; j < 32; j++) {
        CP_WAIT0();
        __syncthreads();   // tile j ready; Q visible (1st iter); stage (j+1)&1 free
        if (j + 1 < 32) {
            int sp = (j + 1) & 1;
            fl_issue_kv(kbase0 + sp * K_FL * 4, vbase0 + sp * V_FL * 4, Kg, Vg,
                        j + 1, tid);
            CP_COMMIT();
        }
        const float* Kc = Ks + (j & 1) * K_FL;
        const float* Vc = Vs + (j & 1) * V_FL;

        // ---- S = Q @ K^T (warp: 16 q rows x 64 keys) ----
        float s[8][4];
#pragma unroll
        for (int nt = 0; nt < 8; nt++) {
            s[nt][0] = s[nt][1] = s[nt][2] = s[nt][3] = 0.f;
        }
#pragma unroll
        for (int kc = 0; kc < 8; kc++) {
            const float4 q0 = *(const float4*)&Qs[((w << 3) + kc) * 128 + lane * 4];
            unsigned aQ[4] = {fb(q0.x), fb(q0.y), fb(q0.z), fb(q0.w)};
            const int kd = kc * 8 + (lane & 3);
#pragma unroll
            for (int nt = 0; nt < 8; nt++) {
                int key = nt * 8 + (lane >> 2);
                unsigned b0 = fb(Kc[key * KST + kd]);
                unsigned b1 = fb(Kc[key * KST + kd + 4]);
                mma_tf32(s[nt], aQ, b0, b1);
            }
        }

        // ---- max (exp2 domain) ----
        float mx[2] = {m[0], m[1]};
#pragma unroll
        for (int nt = 0; nt < 8; nt++) {
            s[nt][0] *= SCALE2; s[nt][1] *= SCALE2;
            s[nt][2] *= SCALE2; s[nt][3] *= SCALE2;
            mx[0] = fmaxf(mx[0], fmaxf(s[nt][0], s[nt][1]));
            mx[1] = fmaxf(mx[1], fmaxf(s[nt][2], s[nt][3]));
        }
#pragma unroll
        for (int hh = 0; hh < 2; hh++) {
            mx[hh] = fmaxf(mx[hh], __shfl_xor_sync(0xffffffffu, mx[hh], 1));
            mx[hh] = fmaxf(mx[hh], __shfl_xor_sync(0xffffffffu, mx[hh], 2));
        }
        float alpha[2];
#pragma unroll
        for (int hh = 0; hh < 2; hh++) {
            alpha[hh] = exp2f(m[hh] - mx[hh]);
            m[hh] = mx[hh];
        }
#pragma unroll
        for (int nt = 0; nt < 8; nt++) {
            o[nt][0] *= alpha[0]; o[nt][1] *= alpha[0];
            o[nt][2] *= alpha[1]; o[nt][3] *= alpha[1];
        }

        // ---- fused exp + transpose + PV mma, per 8-key group ----
        float sum[2] = {0.f, 0.f};
#pragma unroll
        for (int kc = 0; kc < 8; kc++) {
            float p0 = exp2f(s[kc][0] - mx[0]);
            float p1 = exp2f(s[kc][1] - mx[0]);
            float p2 = exp2f(s[kc][2] - mx[1]);
            float p3 = exp2f(s[kc][3] - mx[1]);
            sum[0] += p0 + p1;
            sum[1] += p2 + p3;
            float t00 = __shfl_sync(0xffffffffu, p0, src0);
            float t01 = __shfl_sync(0xffffffffu, p1, src0);
            float t10 = __shfl_sync(0xffffffffu, p2, src0);
            float t11 = __shfl_sync(0xffffffffu, p3, src0);
            float u00 = __shfl_sync(0xffffffffu, p0, src1);
            float u01 = __shfl_sync(0xffffffffu, p1, src1);
            float u10 = __shfl_sync(0xffffffffu, p2, src1);
            float u11 = __shfl_sync(0xffffffffu, p3, src1);
            unsigned aP[4];
            aP[0] = fb(odd ? t01 : t00);
            aP[1] = fb(odd ? t11 : t10);
            aP[2] = fb(odd ? u01 : u00);
            aP[3] = fb(odd ? u11 : u10);
            const int kk = kc * 8 + (lane & 3);
#pragma unroll
            for (int nt = 0; nt < 8; nt++) {
                int cc = nt * 8 + (lane >> 2);
                unsigned b0 = fb(Vc[kk * VST + cc]);
                unsigned b1 = fb(Vc[(kk + 4) * VST + cc]);
                mma_tf32(o[nt], aP, b0, b1);
            }
        }
        // quad-reduce partial row sums, fold into l
#pragma unroll
        for (int hh = 0; hh < 2; hh++) {
            sum[hh] += __shfl_xor_sync(0xffffffffu, sum[hh], 1);
            sum[hh] += __shfl_xor_sync(0xffffffffu, sum[hh], 2);
            l[hh] = l[hh] * alpha[hh] + sum[hh];
        }
    }

    // ---- epilogue: normalize, round, write g_o ----
    const int b = bh >> 4, hd = bh & 15;
    const float inv0 = 1.f / l[0], inv1 = 1.f / l[1];
    size_t row0 = (size_t)b * SEQT + qt * 128 + w * 16 + (lane >> 2);
#pragma unroll
    for (int nt = 0; nt < 8; nt++) {
        int cc = hd * DH + nt * 8 + 2 * (lane & 3);
        g_o[row0 * DMODEL + cc]           = tf32r(o[nt][0] * inv0);
        g_o[row0 * DMODEL + cc + 1]       = tf32r(o[nt][1] * inv0);
        g_o[(row0 + 8) * DMODEL + cc]     = tf32r(o[nt][2] * inv1);
        g_o[(row0 + 8) * DMODEL + cc + 1] = tf32r(o[nt][3] * inv1);
    }
}

// ---------------------------------------------------------------------------
extern "C" void kernel_launch(void* const* d_in, const int* in_sizes, int n_in,
                              void* d_out, int out_size) {
    const float* x     = (const float*)d_in[0];  // [4,2048,1024]
    const float* w_qkv = (const float*)d_in[1];  // [1024,3072]
    const float* w_out = (const float*)d_in[2];  // [1024,1024]
    float* out = (float*)d_out;                  // [4,2048,1024]

    round_x <<<MROWS * DMODEL / 4 / 256, 256>>>((const float4*)x);
    round_wq<<<3 * DMODEL * DMODEL / 4 / 256, 256>>>((const float4*)w_qkv);
    round_wo<<<DMODEL * DMODEL / 4 / 256, 256>>>((const float4*)w_out);

    cudaFuncSetAttribute(gemm_tf32, cudaFuncAttributeMaxDynamicSharedMemorySize,
                         G_SMEM);
    cudaFuncSetAttribute(flash_attn, cudaFuncAttributeMaxDynamicSharedMemorySize,
                         FL_SMEM);

    // K1: QKV projection, scatter + round epilogue
    gemm_tf32<<<dim3(3 * DMODEL / 128, MROWS / 128), 128, G_SMEM>>>(nullptr,
                                                                    3 * DMODEL, 1);
    // K2: flash attention
    flash_attn<<<dim3(BHEADS, SEQT / 128), 256, FL_SMEM>>>();

    // K3: output projection
    gemm_tf32<<<dim3(DMODEL / 128, MROWS / 128), 128, G_SMEM>>>(out, DMODEL, 0);
}

// round 13
// speedup vs baseline: 2.2000x; 1.5778x over previous
#include <cuda_runtime.h>
#include <cuda_fp16.h>
#include <cstdint>

#define HEADS   16
#define DH      64
#define SEQT    2048
#define BATCH   4
#define DMODEL  1024
#define KDIM    1024
#define BHEADS  (BATCH * HEADS)   // 64
#define MROWS   (BATCH * SEQT)    // 8192

__device__ __half g_qh[(size_t)BHEADS * SEQT * DH];          // [bh][t][dh]
__device__ __half g_kh[(size_t)BHEADS * SEQT * DH];          // [bh][t][dh]
__device__ __half g_vT[(size_t)BHEADS * DH * SEQT];          // [bh][dh][t]  (transposed!)
__device__ __half g_oh[(size_t)MROWS * DMODEL];              // [m][1024]
__device__ __half g_xh[(size_t)MROWS * DMODEL];              // rounded x
__device__ __half g_wqT[(size_t)3 * DMODEL * DMODEL];        // [3072][1024] n-major
__device__ __half g_woT[(size_t)DMODEL * DMODEL];            // [1024][1024] n-major

// ---------------- helpers ----------------
__device__ __forceinline__ unsigned pack_f16x2(float lo, float hi) {
    unsigned d;
    asm("cvt.rn.f16x2.f32 %0, %1, %2;" : "=r"(d) : "f"(hi), "f"(lo));
    return d;  // d.lo = lo, d.hi = hi  (memory order: lo first)
}
__device__ __forceinline__ uint32_t smem_u32(const void* p) {
    uint32_t a;
    asm("{ .reg .u64 t; cvta.to.shared.u64 t, %1; cvt.u32.u64 %0, t; }"
        : "=r"(a) : "l"(p));
    return a;
}

#define CP16(dst, src) \
    asm volatile("cp.async.cg.shared.global [%0], [%1], 16;" \
                 :: "r"(dst), "l"(src) : "memory")
#define CP_COMMIT() asm volatile("cp.async.commit_group;" ::: "memory")
#define CP_WAIT0()  asm volatile("cp.async.wait_group 0;" ::: "memory")

// m16n8k16 fp16 mma, fp32 accumulate
__device__ __forceinline__ void mma_f16(float* c, const unsigned* a,
                                        unsigned b0, unsigned b1) {
    asm volatile(
        "mma.sync.aligned.m16n8k16.row.col.f32.f16.f16.f32 "
        "{%0,%1,%2,%3},{%4,%5,%6,%7},{%8,%9},{%0,%1,%2,%3};\n"
        : "+f"(c[0]), "+f"(c[1]), "+f"(c[2]), "+f"(c[3])
        : "r"(a[0]), "r"(a[1]), "r"(a[2]), "r"(a[3]), "r"(b0), "r"(b1));
}

// ---------------- prep: fp16 rounding (+ weight transpose to n-major) ------
__global__ void round_xh(const float4* __restrict__ src) {
    int i = blockIdx.x * blockDim.x + threadIdx.x;
    float4 v = src[i];
    uint2 h;
    h.x = pack_f16x2(v.x, v.y);
    h.y = pack_f16x2(v.z, v.w);
    ((uint2*)g_xh)[i] = h;
}
// src [K][N] f32 row-major -> dst [N][K] half (k-contiguous rows)
__global__ __launch_bounds__(256) void tr_wq(const float* __restrict__ src) {
    __shared__ float tile[32][33];
    const int n0 = blockIdx.x * 32, k0 = blockIdx.y * 32;
    const int tx = threadIdx.x & 31, ty = threadIdx.x >> 5;
#pragma unroll
    for (int i = ty; i < 32; i += 8)
        tile[i][tx] = src[(size_t)(k0 + i) * (3 * DMODEL) + n0 + tx];
    __syncthreads();
#pragma unroll
    for (int i = ty; i < 32; i += 8)
        g_wqT[(size_t)(n0 + i) * KDIM + k0 + tx] = __float2half_rn(tile[tx][i]);
}
__global__ __launch_bounds__(256) void tr_wo(const float* __restrict__ src) {
    __shared__ float tile[32][33];
    const int n0 = blockIdx.x * 32, k0 = blockIdx.y * 32;
    const int tx = threadIdx.x & 31, ty = threadIdx.x >> 5;
#pragma unroll
    for (int i = ty; i < 32; i += 8)
        tile[i][tx] = src[(size_t)(k0 + i) * DMODEL + n0 + tx];
    __syncthreads();
#pragma unroll
    for (int i = ty; i < 32; i += 8)
        g_woT[(size_t)(n0 + i) * KDIM + k0 + tx] = __float2half_rn(tile[tx][i]);
}

// ---------------------------------------------------------------------------
// GEMM fp16: C[M][N] = A[M][1024] @ B'[N][1024]^T (both k-contiguous half).
// BM=128 BN=128 BK=32, 128 threads (4 warps 2x2), warp tile 64x64,
// m16n8k16. 2-stage cp.async ring (40KB) + launch_bounds(128,3).
//   mode 1: A=g_xh, B=g_wqT, N=3072, scatter epilogue -> g_qh/g_kh/g_vT
//   mode 0: A=g_oh, B=g_woT, N=1024, f32 store to C
// ---------------------------------------------------------------------------
#define BK      32
#define STRH    40                         // halfs per smem row (80B)
#define TILE_B  (128 * STRH * 2)           // 10240 B per A or B tile
#define STG_B   (2 * TILE_B)               // 20480 B per stage
#define G_SMEM  (2 * STG_B)                // 40960 B

__device__ __forceinline__ void g_load_slice(uint32_t sbase,
                                             const __half* __restrict__ A,
                                             const __half* __restrict__ B,
                                             int bm, int bn, int kt, int tid) {
    const uint32_t sa = sbase;
    const uint32_t sb = sbase + TILE_B;
#pragma unroll
    for (int p = 0; p < 4; p++) {           // A: 128 rows x 4 chunks
        int idx = tid + 128 * p;
        int r = idx >> 2, c = idx & 3;
        CP16(sa + r * 80 + c * 16,
             A + (size_t)(bm * 128 + r) * KDIM + kt * 32 + c * 8);
    }
#pragma unroll
    for (int p = 0; p < 4; p++) {           // B: 128 n-rows x 4 chunks
        int idx = tid + 128 * p;
        int n = idx >> 2, c = idx & 3;
        CP16(sb + n * 80 + c * 16,
             B + (size_t)(bn * 128 + n) * KDIM + kt * 32 + c * 8);
    }
}

__global__ __launch_bounds__(128, 3) void gemm_f16(float* __restrict__ C, int N,
                                                   int mode) {
    extern __shared__ __half smh[];
    const uint32_t sm0 = smem_u32(smh);

    const int tid = threadIdx.x, lane = tid & 31, wid = tid >> 5;
    const int wm = wid >> 1, wn = wid & 1;
    const int bn = blockIdx.x, bm = blockIdx.y;

    const __half* A = mode ? g_xh : g_oh;
    const __half* B = mode ? g_wqT : g_woT;

    float acc[4][8][4];
#pragma unroll
    for (int mt = 0; mt < 4; mt++)
#pragma unroll
        for (int nt = 0; nt < 8; nt++)
#pragma unroll
            for (int i = 0; i < 4; i++) acc[mt][nt][i] = 0.f;

    g_load_slice(sm0, A, B, bm, bn, 0, tid); CP_COMMIT();

    const int NSL = KDIM / BK;   // 32
    for (int j = 0; j < NSL; j++) {
        CP_WAIT0();
        __syncthreads();
        if (j + 1 < NSL) {
            g_load_slice(sm0 + ((j + 1) & 1) * STG_B, A, B, bm, bn, j + 1, tid);
            CP_COMMIT();
        }

        const __half* As_ = smh + (j & 1) * (STG_B / 2);
        const __half* Bs_ = As_ + (TILE_B / 2);
#pragma unroll
        for (int kc = 0; kc < 2; kc++) {
            const int kb = kc * 16 + 2 * (lane & 3);
            unsigned a[4][4];
#pragma unroll
            for (int mt = 0; mt < 4; mt++) {
                int r = wm * 64 + mt * 16 + (lane >> 2);
                a[mt][0] = *(const unsigned*)&As_[r * STRH + kb];
                a[mt][1] = *(const unsigned*)&As_[(r + 8) * STRH + kb];
                a[mt][2] = *(const unsigned*)&As_[r * STRH + kb + 8];
                a[mt][3] = *(const unsigned*)&As_[(r + 8) * STRH + kb + 8];
            }
            unsigned b[8][2];
#pragma unroll
            for (int nt = 0; nt < 8; nt++) {
                int cc = wn * 64 + nt * 8 + (lane >> 2);
                b[nt][0] = *(const unsigned*)&Bs_[cc * STRH + kb];
                b[nt][1] = *(const unsigned*)&Bs_[cc * STRH + kb + 8];
            }
#pragma unroll
            for (int mt = 0; mt < 4; mt++)
#pragma unroll
                for (int nt = 0; nt < 8; nt++)
                    mma_f16(acc[mt][nt], a[mt], b[nt][0], b[nt][1]);
        }
    }

    // epilogue
#pragma unroll
    for (int mt = 0; mt < 4; mt++) {
#pragma unroll
        for (int nt = 0; nt < 8; nt++) {
            int rbase = bm * 128 + wm * 64 + mt * 16 + (lane >> 2);
            int cbase = bn * 128 + wn * 64 + nt * 8 + 2 * (lane & 3);
#pragma unroll
            for (int i = 0; i < 4; i++) {
                int rr = rbase + ((i >= 2) ? 8 : 0);
                int cc = cbase + (i & 1);
                float v = acc[mt][nt][i];
                if (mode == 0) {
                    C[(size_t)rr * N + cc] = v;
                } else {
                    int b = rr >> 11, t = rr & 2047;
                    int which = cc >> 10, rem = cc & 1023;
                    int h = rem >> 6, dd = rem & 63;
                    size_t bh = (size_t)(b * HEADS + h);
                    __half hv = __float2half_rn(v);
                    if (which == 0)      g_qh[(bh * SEQT + t) * DH + dd] = hv;
                    else if (which == 1) g_kh[(bh * SEQT + t) * DH + dd] = hv;
                    else                 g_vT[(bh * DH + dd) * SEQT + t] = hv;
                }
            }
        }
    }
}

// ---------------------------------------------------------------------------
// Flash attention fp16. Grid (bh=64, qt=8), 256 threads / 8 warps, warp = 32
// q rows (mt=2). Q fragments live in registers (loaded from g_qh). K/V:
// 2-stage cp.async ring, K key-major [64][72], V dh-major [64][72] (from
// g_vT). exp2 softmax; PV A-frag built from S C-frag by f16x2 packs (no
// shuffles). 36,864 B smem.
// ---------------------------------------------------------------------------
#define KSTH   72
#define KT_B   (64 * KSTH * 2)            // 9216 B per K or V tile
#define FL_SMEM (2 * 2 * KT_B)            // 36,864 B

__device__ __forceinline__ void fl_issue_kv(uint32_t kbase, uint32_t vbase,
                                            const __half* __restrict__ Kg,
                                            const __half* __restrict__ Vt,
                                            int tile, int tid) {
#pragma unroll
    for (int p = 0; p < 2; p++) {          // K: 64 rows x 8 chunks = 512
        int idx = tid + 256 * p;
        int row = idx >> 3, c = idx & 7;
        CP16(kbase + row * 144 + c * 16,
             Kg + (size_t)(tile * 64 + row) * DH + c * 8);
    }
#pragma unroll
    for (int p = 0; p < 2; p++) {          // V: 64 dh-rows x 8 chunks
        int idx = tid + 256 * p;
        int row = idx >> 3, c = idx & 7;   // row = dh
        CP16(vbase + row * 144 + c * 16,
             Vt + (size_t)row * SEQT + tile * 64 + c * 8);
    }
}

__global__ __launch_bounds__(256, 1) void flash_attn() {
    extern __shared__ __half smh[];
    const uint32_t sm0 = smem_u32(smh);
    const uint32_t kbase0 = sm0;
    const uint32_t vbase0 = sm0 + 2 * KT_B;
    __half* Ks = smh;
    __half* Vs = smh + 2 * (KT_B / 2);

    const int bh = blockIdx.x, qt = blockIdx.y;
    const int tid = threadIdx.x, lane = tid & 31, w = tid >> 5;

    const __half* Qg = g_qh + ((size_t)bh * SEQT + qt * 256) * DH;
    const __half* Kg = g_kh + (size_t)bh * SEQT * DH;
    const __half* Vt = g_vT + (size_t)bh * DH * SEQT;

    fl_issue_kv(kbase0, vbase0, Kg, Vt, 0, tid); CP_COMMIT();

    // ---- Q fragments in registers: 2 mt x 4 kc x 4 regs ----
    unsigned qf[2][4][4];
#pragma unroll
    for (int mt = 0; mt < 2; mt++) {
        const int r = w * 32 + mt * 16 + (lane >> 2);
#pragma unroll
        for (int kc = 0; kc < 4; kc++) {
            const int kb = kc * 16 + 2 * (lane & 3);
            qf[mt][kc][0] = *(const unsigned*)&Qg[(size_t)r * DH + kb];
            qf[mt][kc][1] = *(const unsigned*)&Qg[(size_t)(r + 8) * DH + kb];
            qf[mt][kc][2] = *(const unsigned*)&Qg[(size_t)r * DH + kb + 8];
            qf[mt][kc][3] = *(const unsigned*)&Qg[(size_t)(r + 8) * DH + kb + 8];
        }
    }

    float m[2][2], l[2][2];
#pragma unroll
    for (int mt = 0; mt < 2; mt++) { m[mt][0] = m[mt][1] = -1e30f; l[mt][0] = l[mt][1] = 0.f; }
    float o[2][8][4];
#pragma unroll
    for (int mt = 0; mt < 2; mt++)
#pragma unroll
        for (int nt = 0; nt < 8; nt++)
#pragma unroll
            for (int i = 0; i < 4; i++) o[mt][nt][i] = 0.f;

    const float SCALE2 = 0.03125f * 1.4426950408889634f;  // 1024^-0.5 * log2(e)

    for (int j = 0; j < 32; j++) {
        CP_WAIT0();
        __syncthreads();
        if (j + 1 < 32) {
            int sp = (j + 1) & 1;
            fl_issue_kv(kbase0 + sp * KT_B, vbase0 + sp * KT_B, Kg, Vt, j + 1, tid);
            CP_COMMIT();
        }
        const __half* Kc = Ks + (j & 1) * (KT_B / 2);
        const __half* Vc = Vs + (j & 1) * (KT_B / 2);

        // ---- S = Q @ K^T ----
        float s[2][8][4];
#pragma unroll
        for (int mt = 0; mt < 2; mt++)
#pragma unroll
            for (int nt = 0; nt < 8; nt++)
#pragma unroll
                for (int i = 0; i < 4; i++) s[mt][nt][i] = 0.f;

#pragma unroll
        for (int kc = 0; kc < 4; kc++) {
            const int kb = kc * 16 + 2 * (lane & 3);
#pragma unroll
            for (int nt = 0; nt < 8; nt++) {
                int key = nt * 8 + (lane >> 2);
                unsigned b0 = *(const unsigned*)&Kc[key * KSTH + kb];
                unsigned b1 = *(const unsigned*)&Kc[key * KSTH + kb + 8];
                mma_f16(s[0][nt], qf[0][kc], b0, b1);
                mma_f16(s[1][nt], qf[1][kc], b0, b1);
            }
        }

        // ---- online max (exp2 domain) ----
        float mx[2][2] = {{m[0][0], m[0][1]}, {m[1][0], m[1][1]}};
#pragma unroll
        for (int mt = 0; mt < 2; mt++)
#pragma unroll
            for (int nt = 0; nt < 8; nt++) {
                s[mt][nt][0] *= SCALE2; s[mt][nt][1] *= SCALE2;
                s[mt][nt][2] *= SCALE2; s[mt][nt][3] *= SCALE2;
                mx[mt][0] = fmaxf(mx[mt][0], fmaxf(s[mt][nt][0], s[mt][nt][1]));
                mx[mt][1] = fmaxf(mx[mt][1], fmaxf(s[mt][nt][2], s[mt][nt][3]));
            }
#pragma unroll
        for (int mt = 0; mt < 2; mt++)
#pragma unroll
            for (int hh = 0; hh < 2; hh++) {
                mx[mt][hh] = fmaxf(mx[mt][hh], __shfl_xor_sync(0xffffffffu, mx[mt][hh], 1));
                mx[mt][hh] = fmaxf(mx[mt][hh], __shfl_xor_sync(0xffffffffu, mx[mt][hh], 2));
            }
        float alpha[2][2];
#pragma unroll
        for (int mt = 0; mt < 2; mt++)
#pragma unroll
            for (int hh = 0; hh < 2; hh++) {
                alpha[mt][hh] = exp2f(m[mt][hh] - mx[mt][hh]);
                m[mt][hh] = mx[mt][hh];
            }
#pragma unroll
        for (int mt = 0; mt < 2; mt++)
#pragma unroll
            for (int nt = 0; nt < 8; nt++) {
                o[mt][nt][0] *= alpha[mt][0]; o[mt][nt][1] *= alpha[mt][0];
                o[mt][nt][2] *= alpha[mt][1]; o[mt][nt][3] *= alpha[mt][1];
            }

        // ---- PV: exp + f16x2 pack (C-frag == A-frag layout; no shuffles) ----
        float sum[2][2] = {{0.f, 0.f}, {0.f, 0.f}};
#pragma unroll
        for (int kc = 0; kc < 4; kc++) {           // keys kc*16 .. +15
            unsigned aP[2][4];
#pragma unroll
            for (int mt = 0; mt < 2; mt++) {
                float pA0 = exp2f(s[mt][2 * kc][0] - mx[mt][0]);
                float pA1 = exp2f(s[mt][2 * kc][1] - mx[mt][0]);
                float pA2 = exp2f(s[mt][2 * kc][2] - mx[mt][1]);
                float pA3 = exp2f(s[mt][2 * kc][3] - mx[mt][1]);
                float pB0 = exp2f(s[mt][2 * kc + 1][0] - mx[mt][0]);
                float pB1 = exp2f(s[mt][2 * kc + 1][1] - mx[mt][0]);
                float pB2 = exp2f(s[mt][2 * kc + 1][2] - mx[mt][1]);
                float pB3 = exp2f(s[mt][2 * kc + 1][3] - mx[mt][1]);
                sum[mt][0] += pA0 + pA1 + pB0 + pB1;
                sum[mt][1] += pA2 + pA3 + pB2 + pB3;
                aP[mt][0] = pack_f16x2(pA0, pA1);   // (row,   k=2q,2q+1)
                aP[mt][1] = pack_f16x2(pA2, pA3);   // (row+8, k=2q,2q+1)
                aP[mt][2] = pack_f16x2(pB0, pB1);   // (row,   k+8)
                aP[mt][3] = pack_f16x2(pB2, pB3);   // (row+8, k+8)
            }
            const int kb = kc * 16 + 2 * (lane & 3);
#pragma unroll
            for (int nt = 0; nt < 8; nt++) {
                int dh = nt * 8 + (lane >> 2);
                unsigned b0 = *(const unsigned*)&Vc[dh * KSTH + kb];
                unsigned b1 = *(const unsigned*)&Vc[dh * KSTH + kb + 8];
                mma_f16(o[0][nt], aP[0], b0, b1);
                mma_f16(o[1][nt], aP[1], b0, b1);
            }
        }
        // quad-reduce row sums, fold into l
#pragma unroll
        for (int mt = 0; mt < 2; mt++)
#pragma unroll
            for (int hh = 0; hh < 2; hh++) {
                sum[mt][hh] += __shfl_xor_sync(0xffffffffu, sum[mt][hh], 1);
                sum[mt][hh] += __shfl_xor_sync(0xffffffffu, sum[mt][hh], 2);
                l[mt][hh] = l[mt][hh] * alpha[mt][hh] + sum[mt][hh];
            }
    }

    // ---- epilogue: normalize, write g_oh (half) ----
    const int b = bh >> 4, hd = bh & 15;
#pragma unroll
    for (int mt = 0; mt < 2; mt++) {
        const float inv0 = 1.f / l[mt][0], inv1 = 1.f / l[mt][1];
        size_t row0 = (size_t)b * SEQT + qt * 256 + w * 32 + mt * 16 + (lane >> 2);
#pragma unroll
        for (int nt = 0; nt < 8; nt++) {
            int cc = hd * DH + nt * 8 + 2 * (lane & 3);
            g_oh[row0 * DMODEL + cc]           = __float2half_rn(o[mt][nt][0] * inv0);
            g_oh[row0 * DMODEL + cc + 1]       = __float2half_rn(o[mt][nt][1] * inv0);
            g_oh[(row0 + 8) * DMODEL + cc]     = __float2half_rn(o[mt][nt][2] * inv1);
            g_oh[(row0 + 8) * DMODEL + cc + 1] = __float2half_rn(o[mt][nt][3] * inv1);
        }
    }
}

// ---------------------------------------------------------------------------
extern "C" void kernel_launch(void* const* d_in, const int* in_sizes, int n_in,
                              void* d_out, int out_size) {
    const float* x     = (const float*)d_in[0];  // [4,2048,1024]
    const float* w_qkv = (const float*)d_in[1];  // [1024,3072]
    const float* w_out = (const float*)d_in[2];  // [1024,1024]
    float* out = (float*)d_out;                  // [4,2048,1024]

    // prep: round to fp16 (11-bit mantissa, same as tf32); weights -> n-major
    round_xh<<<MROWS * DMODEL / 4 / 256, 256>>>((const float4*)x);
    tr_wq<<<dim3(3 * DMODEL / 32, DMODEL / 32), 256>>>(w_qkv);
    tr_wo<<<dim3(DMODEL / 32, DMODEL / 32), 256>>>(w_out);

    cudaFuncSetAttribute(gemm_f16, cudaFuncAttributeMaxDynamicSharedMemorySize,
                         G_SMEM);
    cudaFuncSetAttribute(flash_attn, cudaFuncAttributeMaxDynamicSharedMemorySize,
                         FL_SMEM);

    // K1: QKV projection, scatter epilogue (V transposed for flash PV)
    gemm_f16<<<dim3(3 * DMODEL / 128, MROWS / 128), 128, G_SMEM>>>(nullptr,
                                                                   3 * DMODEL, 1);
    // K2: flash attention
    flash_attn<<<dim3(BHEADS, SEQT / 256), 256, FL_SMEM>>>();

    // K3: output projection (f32 result)
    gemm_f16<<<dim3(DMODEL / 128, MROWS / 128), 128, G_SMEM>>>(out, DMODEL, 0);
}

// round 14
// speedup vs baseline: 2.2746x; 1.0339x over previous
#include <cuda_runtime.h>
#include <cuda_fp16.h>
#include <cstdint>

#define HEADS   16
#define DH      64
#define SEQT    2048
#define BATCH   4
#define DMODEL  1024
#define KDIM    1024
#define BHEADS  (BATCH * HEADS)   // 64
#define MROWS   (BATCH * SEQT)    // 8192

__device__ __half g_qh[(size_t)BHEADS * SEQT * DH];          // [bh][t][dh]
__device__ __half g_kh[(size_t)BHEADS * SEQT * DH];          // [bh][t][dh]
__device__ __half g_vT[(size_t)BHEADS * DH * SEQT];          // [bh][dh][t]  (transposed!)
__device__ __half g_oh[(size_t)MROWS * DMODEL];              // [m][1024]
__device__ __half g_xh[(size_t)MROWS * DMODEL];              // rounded x
__device__ __half g_wqT[(size_t)3 * DMODEL * DMODEL];        // [3072][1024] n-major
__device__ __half g_woT[(size_t)DMODEL * DMODEL];            // [1024][1024] n-major

// ---------------- helpers ----------------
__device__ __forceinline__ unsigned pack_f16x2(float lo, float hi) {
    unsigned d;
    asm("cvt.rn.f16x2.f32 %0, %1, %2;" : "=r"(d) : "f"(hi), "f"(lo));
    return d;  // d.lo = lo, d.hi = hi  (memory order: lo first)
}
__device__ __forceinline__ uint32_t smem_u32(const void* p) {
    uint32_t a;
    asm("{ .reg .u64 t; cvta.to.shared.u64 t, %1; cvt.u32.u64 %0, t; }"
        : "=r"(a) : "l"(p));
    return a;
}

#define CP16(dst, src) \
    asm volatile("cp.async.cg.shared.global [%0], [%1], 16;" \
                 :: "r"(dst), "l"(src) : "memory")
#define CP_COMMIT() asm volatile("cp.async.commit_group;" ::: "memory")
#define CP_WAIT0()  asm volatile("cp.async.wait_group 0;" ::: "memory")

// m16n8k16 fp16 mma, fp32 accumulate
__device__ __forceinline__ void mma_f16(float* c, const unsigned* a,
                                        unsigned b0, unsigned b1) {
    asm volatile(
        "mma.sync.aligned.m16n8k16.row.col.f32.f16.f16.f32 "
        "{%0,%1,%2,%3},{%4,%5,%6,%7},{%8,%9},{%0,%1,%2,%3};\n"
        : "+f"(c[0]), "+f"(c[1]), "+f"(c[2]), "+f"(c[3])
        : "r"(a[0]), "r"(a[1]), "r"(a[2]), "r"(a[3]), "r"(b0), "r"(b1));
}

// ---------------- prep: fp16 rounding (+ weight transpose to n-major) ------
__global__ void round_xh(const float4* __restrict__ src) {
    int i = blockIdx.x * blockDim.x + threadIdx.x;
    float4 v = src[i];
    uint2 h;
    h.x = pack_f16x2(v.x, v.y);
    h.y = pack_f16x2(v.z, v.w);
    ((uint2*)g_xh)[i] = h;
}
// src [K][N] f32 row-major -> dst [N][K] half (k-contiguous rows)
__global__ __launch_bounds__(256) void tr_wq(const float* __restrict__ src) {
    __shared__ float tile[32][33];
    const int n0 = blockIdx.x * 32, k0 = blockIdx.y * 32;
    const int tx = threadIdx.x & 31, ty = threadIdx.x >> 5;
#pragma unroll
    for (int i = ty; i < 32; i += 8)
        tile[i][tx] = src[(size_t)(k0 + i) * (3 * DMODEL) + n0 + tx];
    __syncthreads();
#pragma unroll
    for (int i = ty; i < 32; i += 8)
        g_wqT[(size_t)(n0 + i) * KDIM + k0 + tx] = __float2half_rn(tile[tx][i]);
}
__global__ __launch_bounds__(256) void tr_wo(const float* __restrict__ src) {
    __shared__ float tile[32][33];
    const int n0 = blockIdx.x * 32, k0 = blockIdx.y * 32;
    const int tx = threadIdx.x & 31, ty = threadIdx.x >> 5;
#pragma unroll
    for (int i = ty; i < 32; i += 8)
        tile[i][tx] = src[(size_t)(k0 + i) * DMODEL + n0 + tx];
    __syncthreads();
#pragma unroll
    for (int i = ty; i < 32; i += 8)
        g_woT[(size_t)(n0 + i) * KDIM + k0 + tx] = __float2half_rn(tile[tx][i]);
}

// ---------------------------------------------------------------------------
// GEMM fp16 (unchanged from R13 pass): BM=BN=128, BK=32, 128 thr, 2-stage
// cp.async ring, launch_bounds(128,3).
// ---------------------------------------------------------------------------
#define BK      32
#define STRH    40                         // halfs per smem row (80B)
#define TILE_B  (128 * STRH * 2)           // 10240 B per A or B tile
#define STG_B   (2 * TILE_B)               // 20480 B per stage
#define G_SMEM  (2 * STG_B)                // 40960 B

__device__ __forceinline__ void g_load_slice(uint32_t sbase,
                                             const __half* __restrict__ A,
                                             const __half* __restrict__ B,
                                             int bm, int bn, int kt, int tid) {
    const uint32_t sa = sbase;
    const uint32_t sb = sbase + TILE_B;
#pragma unroll
    for (int p = 0; p < 4; p++) {           // A: 128 rows x 4 chunks
        int idx = tid + 128 * p;
        int r = idx >> 2, c = idx & 3;
        CP16(sa + r * 80 + c * 16,
             A + (size_t)(bm * 128 + r) * KDIM + kt * 32 + c * 8);
    }
#pragma unroll
    for (int p = 0; p < 4; p++) {           // B: 128 n-rows x 4 chunks
        int idx = tid + 128 * p;
        int n = idx >> 2, c = idx & 3;
        CP16(sb + n * 80 + c * 16,
             B + (size_t)(bn * 128 + n) * KDIM + kt * 32 + c * 8);
    }
}

__global__ __launch_bounds__(128, 3) void gemm_f16(float* __restrict__ C, int N,
                                                   int mode) {
    extern __shared__ __half smh[];
    const uint32_t sm0 = smem_u32(smh);

    const int tid = threadIdx.x, lane = tid & 31, wid = tid >> 5;
    const int wm = wid >> 1, wn = wid & 1;
    const int bn = blockIdx.x, bm = blockIdx.y;

    const __half* A = mode ? g_xh : g_oh;
    const __half* B = mode ? g_wqT : g_woT;

    float acc[4][8][4];
#pragma unroll
    for (int mt = 0; mt < 4; mt++)
#pragma unroll
        for (int nt = 0; nt < 8; nt++)
#pragma unroll
            for (int i = 0; i < 4; i++) acc[mt][nt][i] = 0.f;

    g_load_slice(sm0, A, B, bm, bn, 0, tid); CP_COMMIT();

    const int NSL = KDIM / BK;   // 32
    for (int j = 0; j < NSL; j++) {
        CP_WAIT0();
        __syncthreads();
        if (j + 1 < NSL) {
            g_load_slice(sm0 + ((j + 1) & 1) * STG_B, A, B, bm, bn, j + 1, tid);
            CP_COMMIT();
        }

        const __half* As_ = smh + (j & 1) * (STG_B / 2);
        const __half* Bs_ = As_ + (TILE_B / 2);
#pragma unroll
        for (int kc = 0; kc < 2; kc++) {
            const int kb = kc * 16 + 2 * (lane & 3);
            unsigned a[4][4];
#pragma unroll
            for (int mt = 0; mt < 4; mt++) {
                int r = wm * 64 + mt * 16 + (lane >> 2);
                a[mt][0] = *(const unsigned*)&As_[r * STRH + kb];
                a[mt][1] = *(const unsigned*)&As_[(r + 8) * STRH + kb];
                a[mt][2] = *(const unsigned*)&As_[r * STRH + kb + 8];
                a[mt][3] = *(const unsigned*)&As_[(r + 8) * STRH + kb + 8];
            }
            unsigned b[8][2];
#pragma unroll
            for (int nt = 0; nt < 8; nt++) {
                int cc = wn * 64 + nt * 8 + (lane >> 2);
                b[nt][0] = *(const unsigned*)&Bs_[cc * STRH + kb];
                b[nt][1] = *(const unsigned*)&Bs_[cc * STRH + kb + 8];
            }
#pragma unroll
            for (int mt = 0; mt < 4; mt++)
#pragma unroll
                for (int nt = 0; nt < 8; nt++)
                    mma_f16(acc[mt][nt], a[mt], b[nt][0], b[nt][1]);
        }
    }

    // epilogue
#pragma unroll
    for (int mt = 0; mt < 4; mt++) {
#pragma unroll
        for (int nt = 0; nt < 8; nt++) {
            int rbase = bm * 128 + wm * 64 + mt * 16 + (lane >> 2);
            int cbase = bn * 128 + wn * 64 + nt * 8 + 2 * (lane & 3);
#pragma unroll
            for (int i = 0; i < 4; i++) {
                int rr = rbase + ((i >= 2) ? 8 : 0);
                int cc = cbase + (i & 1);
                float v = acc[mt][nt][i];
                if (mode == 0) {
                    C[(size_t)rr * N + cc] = v;
                } else {
                    int b = rr >> 11, t = rr & 2047;
                    int which = cc >> 10, rem = cc & 1023;
                    int h = rem >> 6, dd = rem & 63;
                    size_t bh = (size_t)(b * HEADS + h);
                    __half hv = __float2half_rn(v);
                    if (which == 0)      g_qh[(bh * SEQT + t) * DH + dd] = hv;
                    else if (which == 1) g_kh[(bh * SEQT + t) * DH + dd] = hv;
                    else                 g_vT[(bh * DH + dd) * SEQT + t] = hv;
                }
            }
        }
    }
}

// ---------------------------------------------------------------------------
// Flash attention fp16 v5. Grid (bh=64, qt=16), 256 threads / 8 warps,
// warp = 16 q rows (q-tile 128). ~120 regs -> launch_bounds(256,2) ->
// 2 CTAs/SM, 4 warps/SMSP; cross-CTA softmax/mma overlap. K/V 2-stage
// cp.async ring, V dh-major from g_vT; exp2 softmax; PV A-frag from S
// C-frag by f16x2 packs. 36,864 B smem.
// ---------------------------------------------------------------------------
#define KSTH   72
#define KT_B   (64 * KSTH * 2)            // 9216 B per K or V tile
#define FL_SMEM (2 * 2 * KT_B)            // 36,864 B

__device__ __forceinline__ void fl_issue_kv(uint32_t kbase, uint32_t vbase,
                                            const __half* __restrict__ Kg,
                                            const __half* __restrict__ Vt,
                                            int tile, int tid) {
#pragma unroll
    for (int p = 0; p < 2; p++) {          // K: 64 rows x 8 chunks = 512
        int idx = tid + 256 * p;
        int row = idx >> 3, c = idx & 7;
        CP16(kbase + row * 144 + c * 16,
             Kg + (size_t)(tile * 64 + row) * DH + c * 8);
    }
#pragma unroll
    for (int p = 0; p < 2; p++) {          // V: 64 dh-rows x 8 chunks
        int idx = tid + 256 * p;
        int row = idx >> 3, c = idx & 7;   // row = dh
        CP16(vbase + row * 144 + c * 16,
             Vt + (size_t)row * SEQT + tile * 64 + c * 8);
    }
}

__global__ __launch_bounds__(256, 2) void flash_attn() {
    extern __shared__ __half smh[];
    const uint32_t sm0 = smem_u32(smh);
    const uint32_t kbase0 = sm0;
    const uint32_t vbase0 = sm0 + 2 * KT_B;
    __half* Ks = smh;
    __half* Vs = smh + 2 * (KT_B / 2);

    const int bh = blockIdx.x, qt = blockIdx.y;
    const int tid = threadIdx.x, lane = tid & 31, w = tid >> 5;

    const __half* Qg = g_qh + ((size_t)bh * SEQT + qt * 128) * DH;
    const __half* Kg = g_kh + (size_t)bh * SEQT * DH;
    const __half* Vt = g_vT + (size_t)bh * DH * SEQT;

    fl_issue_kv(kbase0, vbase0, Kg, Vt, 0, tid); CP_COMMIT();

    // ---- Q fragments in registers: 4 kc x 4 regs (warp = 16 q rows) ----
    unsigned qf[4][4];
    {
        const int r = w * 16 + (lane >> 2);
#pragma unroll
        for (int kc = 0; kc < 4; kc++) {
            const int kb = kc * 16 + 2 * (lane & 3);
            qf[kc][0] = *(const unsigned*)&Qg[(size_t)r * DH + kb];
            qf[kc][1] = *(const unsigned*)&Qg[(size_t)(r + 8) * DH + kb];
            qf[kc][2] = *(const unsigned*)&Qg[(size_t)r * DH + kb + 8];
            qf[kc][3] = *(const unsigned*)&Qg[(size_t)(r + 8) * DH + kb + 8];
        }
    }

    float m[2] = {-1e30f, -1e30f}, l[2] = {0.f, 0.f};
    float o[8][4];
#pragma unroll
    for (int nt = 0; nt < 8; nt++)
#pragma unroll
        for (int i = 0; i < 4; i++) o[nt][i] = 0.f;

    const float SCALE2 = 0.03125f * 1.4426950408889634f;  // 1024^-0.5 * log2(e)

    for (int j = 0; j < 32; j++) {
        CP_WAIT0();
        __syncthreads();
        if (j + 1 < 32) {
            int sp = (j + 1) & 1;
            fl_issue_kv(kbase0 + sp * KT_B, vbase0 + sp * KT_B, Kg, Vt, j + 1, tid);
            CP_COMMIT();
        }
        const __half* Kc = Ks + (j & 1) * (KT_B / 2);
        const __half* Vc = Vs + (j & 1) * (KT_B / 2);

        // ---- S = Q @ K^T (16 q rows x 64 keys per warp) ----
        float s[8][4];
#pragma unroll
        for (int nt = 0; nt < 8; nt++) {
            s[nt][0] = s[nt][1] = s[nt][2] = s[nt][3] = 0.f;
        }
#pragma unroll
        for (int kc = 0; kc < 4; kc++) {
            const int kb = kc * 16 + 2 * (lane & 3);
#pragma unroll
            for (int nt = 0; nt < 8; nt++) {
                int key = nt * 8 + (lane >> 2);
                unsigned b0 = *(const unsigned*)&Kc[key * KSTH + kb];
                unsigned b1 = *(const unsigned*)&Kc[key * KSTH + kb + 8];
                mma_f16(s[nt], qf[kc], b0, b1);
            }
        }

        // ---- online max (exp2 domain) ----
        float mx[2] = {m[0], m[1]};
#pragma unroll
        for (int nt = 0; nt < 8; nt++) {
            s[nt][0] *= SCALE2; s[nt][1] *= SCALE2;
            s[nt][2] *= SCALE2; s[nt][3] *= SCALE2;
            mx[0] = fmaxf(mx[0], fmaxf(s[nt][0], s[nt][1]));
            mx[1] = fmaxf(mx[1], fmaxf(s[nt][2], s[nt][3]));
        }
#pragma unroll
        for (int hh = 0; hh < 2; hh++) {
            mx[hh] = fmaxf(mx[hh], __shfl_xor_sync(0xffffffffu, mx[hh], 1));
            mx[hh] = fmaxf(mx[hh], __shfl_xor_sync(0xffffffffu, mx[hh], 2));
        }
        float alpha[2];
#pragma unroll
        for (int hh = 0; hh < 2; hh++) {
            alpha[hh] = exp2f(m[hh] - mx[hh]);
            m[hh] = mx[hh];
        }
#pragma unroll
        for (int nt = 0; nt < 8; nt++) {
            o[nt][0] *= alpha[0]; o[nt][1] *= alpha[0];
            o[nt][2] *= alpha[1]; o[nt][3] *= alpha[1];
        }

        // ---- PV: exp + f16x2 pack (C-frag == A-frag layout; no shuffles) ----
        float sum[2] = {0.f, 0.f};
#pragma unroll
        for (int kc = 0; kc < 4; kc++) {           // keys kc*16 .. +15
            float pA0 = exp2f(s[2 * kc][0] - mx[0]);
            float pA1 = exp2f(s[2 * kc][1] - mx[0]);
            float pA2 = exp2f(s[2 * kc][2] - mx[1]);
            float pA3 = exp2f(s[2 * kc][3] - mx[1]);
            float pB0 = exp2f(s[2 * kc + 1][0] - mx[0]);
            float pB1 = exp2f(s[2 * kc + 1][1] - mx[0]);
            float pB2 = exp2f(s[2 * kc + 1][2] - mx[1]);
            float pB3 = exp2f(s[2 * kc + 1][3] - mx[1]);
            sum[0] += pA0 + pA1 + pB0 + pB1;
            sum[1] += pA2 + pA3 + pB2 + pB3;
            unsigned aP[4];
            aP[0] = pack_f16x2(pA0, pA1);   // (row,   k=2q,2q+1)
            aP[1] = pack_f16x2(pA2, pA3);   // (row+8, k=2q,2q+1)
            aP[2] = pack_f16x2(pB0, pB1);   // (row,   k+8)
            aP[3] = pack_f16x2(pB2, pB3);   // (row+8, k+8)
            const int kb = kc * 16 + 2 * (lane & 3);
#pragma unroll
            for (int nt = 0; nt < 8; nt++) {
                int dh = nt * 8 + (lane >> 2);
                unsigned b0 = *(const unsigned*)&Vc[dh * KSTH + kb];
                unsigned b1 = *(const unsigned*)&Vc[dh * KSTH + kb + 8];
                mma_f16(o[nt], aP, b0, b1);
            }
        }
        // quad-reduce row sums, fold into l
#pragma unroll
        for (int hh = 0; hh < 2; hh++) {
            sum[hh] += __shfl_xor_sync(0xffffffffu, sum[hh], 1);
            sum[hh] += __shfl_xor_sync(0xffffffffu, sum[hh], 2);
            l[hh] = l[hh] * alpha[hh] + sum[hh];
        }
    }

    // ---- epilogue: normalize, write g_oh (half) ----
    const int b = bh >> 4, hd = bh & 15;
    const float inv0 = 1.f / l[0], inv1 = 1.f / l[1];
    size_t row0 = (size_t)b * SEQT + qt * 128 + w * 16 + (lane >> 2);
#pragma unroll
    for (int nt = 0; nt < 8; nt++) {
        int cc = hd * DH + nt * 8 + 2 * (lane & 3);
        g_oh[row0 * DMODEL + cc]           = __float2half_rn(o[nt][0] * inv0);
        g_oh[row0 * DMODEL + cc + 1]       = __float2half_rn(o[nt][1] * inv0);
        g_oh[(row0 + 8) * DMODEL + cc]     = __float2half_rn(o[nt][2] * inv1);
        g_oh[(row0 + 8) * DMODEL + cc + 1] = __float2half_rn(o[nt][3] * inv1);
    }
}

// ---------------------------------------------------------------------------
extern "C" void kernel_launch(void* const* d_in, const int* in_sizes, int n_in,
                              void* d_out, int out_size) {
    const float* x     = (const float*)d_in[0];  // [4,2048,1024]
    const float* w_qkv = (const float*)d_in[1];  // [1024,3072]
    const float* w_out = (const float*)d_in[2];  // [1024,1024]
    float* out = (float*)d_out;                  // [4,2048,1024]

    // prep: round to fp16; weights -> n-major
    round_xh<<<MROWS * DMODEL / 4 / 256, 256>>>((const float4*)x);
    tr_wq<<<dim3(3 * DMODEL / 32, DMODEL / 32), 256>>>(w_qkv);
    tr_wo<<<dim3(DMODEL / 32, DMODEL / 32), 256>>>(w_out);

    cudaFuncSetAttribute(gemm_f16, cudaFuncAttributeMaxDynamicSharedMemorySize,
                         G_SMEM);
    cudaFuncSetAttribute(flash_attn, cudaFuncAttributeMaxDynamicSharedMemorySize,
                         FL_SMEM);

    // K1: QKV projection, scatter epilogue (V transposed for flash PV)
    gemm_f16<<<dim3(3 * DMODEL / 128, MROWS / 128), 128, G_SMEM>>>(nullptr,
                                                                   3 * DMODEL, 1);
    // K2: flash attention (q-tile 128, 2 CTAs/SM)
    flash_attn<<<dim3(BHEADS, SEQT / 128), 256, FL_SMEM>>>();

    // K3: output projection (f32 result)
    gemm_f16<<<dim3(DMODEL / 128, MROWS / 128), 128, G_SMEM>>>(out, DMODEL, 0);
}

// round 15
// speedup vs baseline: 2.4172x; 1.0627x over previous
#include <cuda_runtime.h>
#include <cuda_fp16.h>
#include <cstdint>

#define HEADS   16
#define DH      64
#define SEQT    2048
#define BATCH   4
#define DMODEL  1024
#define KDIM    1024
#define BHEADS  (BATCH * HEADS)   // 64
#define MROWS   (BATCH * SEQT)    // 8192

__device__ __half g_qh[(size_t)BHEADS * SEQT * DH];          // [bh][t][dh]
__device__ __half g_kh[(size_t)BHEADS * SEQT * DH];          // [bh][t][dh]
__device__ __half g_vT[(size_t)BHEADS * DH * SEQT];          // [bh][dh][t]
__device__ __half g_oh[(size_t)MROWS * DMODEL];              // [m][1024]
__device__ __half g_xh[(size_t)MROWS * DMODEL];              // rounded x
__device__ __half g_wqT[(size_t)3 * DMODEL * DMODEL];        // [3072][1024] n-major
__device__ __half g_woT[(size_t)DMODEL * DMODEL];            // [1024][1024] n-major

// ---------------- helpers ----------------
__device__ __forceinline__ unsigned pack_f16x2(float lo, float hi) {
    unsigned d;
    asm("cvt.rn.f16x2.f32 %0, %1, %2;" : "=r"(d) : "f"(hi), "f"(lo));
    return d;
}
__device__ __forceinline__ uint32_t smem_u32(const void* p) {
    uint32_t a;
    asm("{ .reg .u64 t; cvta.to.shared.u64 t, %1; cvt.u32.u64 %0, t; }"
        : "=r"(a) : "l"(p));
    return a;
}

#define CP16(dst, src) \
    asm volatile("cp.async.cg.shared.global [%0], [%1], 16;" \
                 :: "r"(dst), "l"(src) : "memory")
#define CP_COMMIT() asm volatile("cp.async.commit_group;" ::: "memory")
#define CP_WAIT0()  asm volatile("cp.async.wait_group 0;" ::: "memory")

// m16n8k16 fp16 mma, fp32 accumulate
__device__ __forceinline__ void mma_f16(float* c, const unsigned* a,
                                        unsigned b0, unsigned b1) {
    asm volatile(
        "mma.sync.aligned.m16n8k16.row.col.f32.f16.f16.f32 "
        "{%0,%1,%2,%3},{%4,%5,%6,%7},{%8,%9},{%0,%1,%2,%3};\n"
        : "+f"(c[0]), "+f"(c[1]), "+f"(c[2]), "+f"(c[3])
        : "r"(a[0]), "r"(a[1]), "r"(a[2]), "r"(a[3]), "r"(b0), "r"(b1));
}

// ldmatrix x4: 4 fragment regs in one LSU op
__device__ __forceinline__ void ldsm_x4(unsigned* r, uint32_t addr) {
    asm volatile(
        "ldmatrix.sync.aligned.m8n8.x4.shared.b16 {%0,%1,%2,%3}, [%4];"
        : "=r"(r[0]), "=r"(r[1]), "=r"(r[2]), "=r"(r[3]) : "r"(addr));
}

// ---------------- prep: fp16 rounding (+ weight transpose to n-major) ------
__global__ void round_xh(const float4* __restrict__ src) {
    int i = blockIdx.x * blockDim.x + threadIdx.x;
    float4 v = src[i];
    uint2 h;
    h.x = pack_f16x2(v.x, v.y);
    h.y = pack_f16x2(v.z, v.w);
    ((uint2*)g_xh)[i] = h;
}
__global__ __launch_bounds__(256) void tr_wq(const float* __restrict__ src) {
    __shared__ float tile[32][33];
    const int n0 = blockIdx.x * 32, k0 = blockIdx.y * 32;
    const int tx = threadIdx.x & 31, ty = threadIdx.x >> 5;
#pragma unroll
    for (int i = ty; i < 32; i += 8)
        tile[i][tx] = src[(size_t)(k0 + i) * (3 * DMODEL) + n0 + tx];
    __syncthreads();
#pragma unroll
    for (int i = ty; i < 32; i += 8)
        g_wqT[(size_t)(n0 + i) * KDIM + k0 + tx] = __float2half_rn(tile[tx][i]);
}
__global__ __launch_bounds__(256) void tr_wo(const float* __restrict__ src) {
    __shared__ float tile[32][33];
    const int n0 = blockIdx.x * 32, k0 = blockIdx.y * 32;
    const int tx = threadIdx.x & 31, ty = threadIdx.x >> 5;
#pragma unroll
    for (int i = ty; i < 32; i += 8)
        tile[i][tx] = src[(size_t)(k0 + i) * DMODEL + n0 + tx];
    __syncthreads();
#pragma unroll
    for (int i = ty; i < 32; i += 8)
        g_woT[(size_t)(n0 + i) * KDIM + k0 + tx] = __float2half_rn(tile[tx][i]);
}

// ---------------------------------------------------------------------------
// GEMM fp16 + LDSM. BM=BN=128, BK=32, 128 thr (4 warps 2x2), warp 64x64,
// 2-stage cp.async ring, launch_bounds(128,3).
// ---------------------------------------------------------------------------
#define BK      32
#define STRH    40                         // halfs per smem row (80B)
#define TILE_B  (128 * STRH * 2)           // 10240 B per A or B tile
#define STG_B   (2 * TILE_B)               // 20480 B per stage
#define G_SMEM  (2 * STG_B)                // 40960 B

__device__ __forceinline__ void g_load_slice(uint32_t sbase,
                                             const __half* __restrict__ A,
                                             const __half* __restrict__ B,
                                             int bm, int bn, int kt, int tid) {
    const uint32_t sa = sbase;
    const uint32_t sb = sbase + TILE_B;
#pragma unroll
    for (int p = 0; p < 4; p++) {
        int idx = tid + 128 * p;
        int r = idx >> 2, c = idx & 3;
        CP16(sa + r * 80 + c * 16,
             A + (size_t)(bm * 128 + r) * KDIM + kt * 32 + c * 8);
    }
#pragma unroll
    for (int p = 0; p < 4; p++) {
        int idx = tid + 128 * p;
        int n = idx >> 2, c = idx & 3;
        CP16(sb + n * 80 + c * 16,
             B + (size_t)(bn * 128 + n) * KDIM + kt * 32 + c * 8);
    }
}

__global__ __launch_bounds__(128, 3) void gemm_f16(float* __restrict__ C, int N,
                                                   int mode) {
    extern __shared__ __half smh[];
    const uint32_t sm0 = smem_u32(smh);

    const int tid = threadIdx.x, lane = tid & 31, wid = tid >> 5;
    const int wm = wid >> 1, wn = wid & 1;
    const int bn = blockIdx.x, bm = blockIdx.y;

    const __half* A = mode ? g_xh : g_oh;
    const __half* B = mode ? g_wqT : g_woT;

    // per-lane LDSM offsets (bytes)
    //   A (mt tile): rows r0m+(lane&15), k-half ((lane>>4)&1)*8
    const uint32_t a_lane = ((lane & 15) * STRH + ((lane >> 4) & 1) * 8) * 2;
    //   B (nt pair): rows n0+((lane>>4)&1)*8+(lane&7), k-half ((lane>>3)&1)*8
    const uint32_t b_lane = ((((lane >> 4) & 1) * 8 + (lane & 7)) * STRH
                             + ((lane >> 3) & 1) * 8) * 2;

    float acc[4][8][4];
#pragma unroll
    for (int mt = 0; mt < 4; mt++)
#pragma unroll
        for (int nt = 0; nt < 8; nt++)
#pragma unroll
            for (int i = 0; i < 4; i++) acc[mt][nt][i] = 0.f;

    g_load_slice(sm0, A, B, bm, bn, 0, tid); CP_COMMIT();

    const int NSL = KDIM / BK;   // 32
    for (int j = 0; j < NSL; j++) {
        CP_WAIT0();
        __syncthreads();
        if (j + 1 < NSL) {
            g_load_slice(sm0 + ((j + 1) & 1) * STG_B, A, B, bm, bn, j + 1, tid);
            CP_COMMIT();
        }

        const uint32_t as0 = sm0 + (j & 1) * STG_B;
        const uint32_t bs0 = as0 + TILE_B;
#pragma unroll
        for (int kc = 0; kc < 2; kc++) {
            const uint32_t kb2 = kc * 16 * 2;      // byte offset of k block
            unsigned a[4][4];
#pragma unroll
            for (int mt = 0; mt < 4; mt++)
                ldsm_x4(a[mt], as0 + (wm * 64 + mt * 16) * (STRH * 2) + kb2 + a_lane);
            unsigned b[8][2];
#pragma unroll
            for (int ntp = 0; ntp < 4; ntp++) {
                unsigned r[4];
                ldsm_x4(r, bs0 + (wn * 64 + ntp * 16) * (STRH * 2) + kb2 + b_lane);
                b[2 * ntp][0] = r[0]; b[2 * ntp][1] = r[1];
                b[2 * ntp + 1][0] = r[2]; b[2 * ntp + 1][1] = r[3];
            }
#pragma unroll
            for (int mt = 0; mt < 4; mt++)
#pragma unroll
                for (int nt = 0; nt < 8; nt++)
                    mma_f16(acc[mt][nt], a[mt], b[nt][0], b[nt][1]);
        }
    }

    // epilogue
#pragma unroll
    for (int mt = 0; mt < 4; mt++) {
#pragma unroll
        for (int nt = 0; nt < 8; nt++) {
            int rbase = bm * 128 + wm * 64 + mt * 16 + (lane >> 2);
            int cbase = bn * 128 + wn * 64 + nt * 8 + 2 * (lane & 3);
#pragma unroll
            for (int i = 0; i < 4; i++) {
                int rr = rbase + ((i >= 2) ? 8 : 0);
                int cc = cbase + (i & 1);
                float v = acc[mt][nt][i];
                if (mode == 0) {
                    C[(size_t)rr * N + cc] = v;
                } else {
                    int b_ = rr >> 11, t = rr & 2047;
                    int which = cc >> 10, rem = cc & 1023;
                    int h = rem >> 6, dd = rem & 63;
                    size_t bh = (size_t)(b_ * HEADS + h);
                    __half hv = __float2half_rn(v);
                    if (which == 0)      g_qh[(bh * SEQT + t) * DH + dd] = hv;
                    else if (which == 1) g_kh[(bh * SEQT + t) * DH + dd] = hv;
                    else                 g_vT[(bh * DH + dd) * SEQT + t] = hv;
                }
            }
        }
    }
}

// ---------------------------------------------------------------------------
// Flash attention fp16 + LDSM. Grid (bh=64, qt=16), 256 thr / 8 warps,
// warp = 16 q rows. K/V 2-stage cp.async ring; K/V frags via ldmatrix.x4;
// exp2 softmax; PV A-frag from S C-frag by f16x2 packs. launch_bounds(256,2).
// ---------------------------------------------------------------------------
#define KSTH   72
#define KT_B   (64 * KSTH * 2)            // 9216 B per K or V tile
#define FL_SMEM (2 * 2 * KT_B)            // 36,864 B

__device__ __forceinline__ void fl_issue_kv(uint32_t kbase, uint32_t vbase,
                                            const __half* __restrict__ Kg,
                                            const __half* __restrict__ Vt,
                                            int tile, int tid) {
#pragma unroll
    for (int p = 0; p < 2; p++) {
        int idx = tid + 256 * p;
        int row = idx >> 3, c = idx & 7;
        CP16(kbase + row * 144 + c * 16,
             Kg + (size_t)(tile * 64 + row) * DH + c * 8);
    }
#pragma unroll
    for (int p = 0; p < 2; p++) {
        int idx = tid + 256 * p;
        int row = idx >> 3, c = idx & 7;
        CP16(vbase + row * 144 + c * 16,
             Vt + (size_t)row * SEQT + tile * 64 + c * 8);
    }
}

__global__ __launch_bounds__(256, 2) void flash_attn() {
    extern __shared__ __half smh[];
    const uint32_t sm0 = smem_u32(smh);
    const uint32_t kbase0 = sm0;
    const uint32_t vbase0 = sm0 + 2 * KT_B;

    const int bh = blockIdx.x, qt = blockIdx.y;
    const int tid = threadIdx.x, lane = tid & 31, w = tid >> 5;

    const __half* Qg = g_qh + ((size_t)bh * SEQT + qt * 128) * DH;
    const __half* Kg = g_kh + (size_t)bh * SEQT * DH;
    const __half* Vt = g_vT + (size_t)bh * DH * SEQT;

    fl_issue_kv(kbase0, vbase0, Kg, Vt, 0, tid); CP_COMMIT();

    // per-lane LDSM offset for K/V nt-pairs (bytes), stride KSTH
    const uint32_t kv_lane = ((((lane >> 4) & 1) * 8 + (lane & 7)) * KSTH
                              + ((lane >> 3) & 1) * 8) * 2;

    // ---- Q fragments in registers ----
    unsigned qf[4][4];
    {
        const int r = w * 16 + (lane >> 2);
#pragma unroll
        for (int kc = 0; kc < 4; kc++) {
            const int kb = kc * 16 + 2 * (lane & 3);
            qf[kc][0] = *(const unsigned*)&Qg[(size_t)r * DH + kb];
            qf[kc][1] = *(const unsigned*)&Qg[(size_t)(r + 8) * DH + kb];
            qf[kc][2] = *(const unsigned*)&Qg[(size_t)r * DH + kb + 8];
            qf[kc][3] = *(const unsigned*)&Qg[(size_t)(r + 8) * DH + kb + 8];
        }
    }

    float m[2] = {-1e30f, -1e30f}, l[2] = {0.f, 0.f};
    float o[8][4];
#pragma unroll
    for (int nt = 0; nt < 8; nt++)
#pragma unroll
        for (int i = 0; i < 4; i++) o[nt][i] = 0.f;

    const float SCALE2 = 0.03125f * 1.4426950408889634f;  // 1024^-0.5 * log2(e)

    for (int j = 0; j < 32; j++) {
        CP_WAIT0();
        __syncthreads();
        if (j + 1 < 32) {
            int sp = (j + 1) & 1;
            fl_issue_kv(kbase0 + sp * KT_B, vbase0 + sp * KT_B, Kg, Vt, j + 1, tid);
            CP_COMMIT();
        }
        const uint32_t kc0 = kbase0 + (j & 1) * KT_B;
        const uint32_t vc0 = vbase0 + (j & 1) * KT_B;

        // ---- S = Q @ K^T ----
        float s[8][4];
#pragma unroll
        for (int nt = 0; nt < 8; nt++) {
            s[nt][0] = s[nt][1] = s[nt][2] = s[nt][3] = 0.f;
        }
#pragma unroll
        for (int kc = 0; kc < 4; kc++) {
            const uint32_t kb2 = kc * 16 * 2;
#pragma unroll
            for (int ntp = 0; ntp < 4; ntp++) {
                unsigned r[4];
                ldsm_x4(r, kc0 + (ntp * 16) * (KSTH * 2) + kb2 + kv_lane);
                mma_f16(s[2 * ntp],     qf[kc], r[0], r[1]);
                mma_f16(s[2 * ntp + 1], qf[kc], r[2], r[3]);
            }
        }

        // ---- online max (exp2 domain) ----
        float mx[2] = {m[0], m[1]};
#pragma unroll
        for (int nt = 0; nt < 8; nt++) {
            s[nt][0] *= SCALE2; s[nt][1] *= SCALE2;
            s[nt][2] *= SCALE2; s[nt][3] *= SCALE2;
            mx[0] = fmaxf(mx[0], fmaxf(s[nt][0], s[nt][1]));
            mx[1] = fmaxf(mx[1], fmaxf(s[nt][2], s[nt][3]));
        }
#pragma unroll
        for (int hh = 0; hh < 2; hh++) {
            mx[hh] = fmaxf(mx[hh], __shfl_xor_sync(0xffffffffu, mx[hh], 1));
            mx[hh] = fmaxf(mx[hh], __shfl_xor_sync(0xffffffffu, mx[hh], 2));
        }
        float alpha[2];
#pragma unroll
        for (int hh = 0; hh < 2; hh++) {
            alpha[hh] = exp2f(m[hh] - mx[hh]);
            m[hh] = mx[hh];
        }
#pragma unroll
        for (int nt = 0; nt < 8; nt++) {
            o[nt][0] *= alpha[0]; o[nt][1] *= alpha[0];
            o[nt][2] *= alpha[1]; o[nt][3] *= alpha[1];
        }

        // ---- PV: exp + f16x2 pack; V frags via LDSM ----
        float sum[2] = {0.f, 0.f};
#pragma unroll
        for (int kc = 0; kc < 4; kc++) {           // keys kc*16 .. +15
            float pA0 = exp2f(s[2 * kc][0] - mx[0]);
            float pA1 = exp2f(s[2 * kc][1] - mx[0]);
            float pA2 = exp2f(s[2 * kc][2] - mx[1]);
            float pA3 = exp2f(s[2 * kc][3] - mx[1]);
            float pB0 = exp2f(s[2 * kc + 1][0] - mx[0]);
            float pB1 = exp2f(s[2 * kc + 1][1] - mx[0]);
            float pB2 = exp2f(s[2 * kc + 1][2] - mx[1]);
            float pB3 = exp2f(s[2 * kc + 1][3] - mx[1]);
            sum[0] += pA0 + pA1 + pB0 + pB1;
            sum[1] += pA2 + pA3 + pB2 + pB3;
            unsigned aP[4];
            aP[0] = pack_f16x2(pA0, pA1);
            aP[1] = pack_f16x2(pA2, pA3);
            aP[2] = pack_f16x2(pB0, pB1);
            aP[3] = pack_f16x2(pB2, pB3);
            const uint32_t kb2 = kc * 16 * 2;
#pragma unroll
            for (int ntp = 0; ntp < 4; ntp++) {    // dh pairs
                unsigned r[4];
                ldsm_x4(r, vc0 + (ntp * 16) * (KSTH * 2) + kb2 + kv_lane);
                mma_f16(o[2 * ntp],     aP, r[0], r[1]);
                mma_f16(o[2 * ntp + 1], aP, r[2], r[3]);
            }
        }
        // quad-reduce row sums, fold into l
#pragma unroll
        for (int hh = 0; hh < 2; hh++) {
            sum[hh] += __shfl_xor_sync(0xffffffffu, sum[hh], 1);
            sum[hh] += __shfl_xor_sync(0xffffffffu, sum[hh], 2);
            l[hh] = l[hh] * alpha[hh] + sum[hh];
        }
    }

    // ---- epilogue: normalize, write g_oh ----
    const int b = bh >> 4, hd = bh & 15;
    const float inv0 = 1.f / l[0], inv1 = 1.f / l[1];
    size_t row0 = (size_t)b * SEQT + qt * 128 + w * 16 + (lane >> 2);
#pragma unroll
    for (int nt = 0; nt < 8; nt++) {
        int cc = hd * DH + nt * 8 + 2 * (lane & 3);
        g_oh[row0 * DMODEL + cc]           = __float2half_rn(o[nt][0] * inv0);
        g_oh[row0 * DMODEL + cc + 1]       = __float2half_rn(o[nt][1] * inv0);
        g_oh[(row0 + 8) * DMODEL + cc]     = __float2half_rn(o[nt][2] * inv1);
        g_oh[(row0 + 8) * DMODEL + cc + 1] = __float2half_rn(o[nt][3] * inv1);
    }
}

// ---------------------------------------------------------------------------
extern "C" void kernel_launch(void* const* d_in, const int* in_sizes, int n_in,
                              void* d_out, int out_size) {
    const float* x     = (const float*)d_in[0];  // [4,2048,1024]
    const float* w_qkv = (const float*)d_in[1];  // [1024,3072]
    const float* w_out = (const float*)d_in[2];  // [1024,1024]
    float* out = (float*)d_out;                  // [4,2048,1024]

    round_xh<<<MROWS * DMODEL / 4 / 256, 256>>>((const float4*)x);
    tr_wq<<<dim3(3 * DMODEL / 32, DMODEL / 32), 256>>>(w_qkv);
    tr_wo<<<dim3(DMODEL / 32, DMODEL / 32), 256>>>(w_out);

    cudaFuncSetAttribute(gemm_f16, cudaFuncAttributeMaxDynamicSharedMemorySize,
                         G_SMEM);
    cudaFuncSetAttribute(flash_attn, cudaFuncAttributeMaxDynamicSharedMemorySize,
                         FL_SMEM);

    // K1: QKV projection, scatter epilogue (V transposed for flash PV)
    gemm_f16<<<dim3(3 * DMODEL / 128, MROWS / 128), 128, G_SMEM>>>(nullptr,
                                                                   3 * DMODEL, 1);
    // K2: flash attention
    flash_attn<<<dim3(BHEADS, SEQT / 128), 256, FL_SMEM>>>();

    // K3: output projection
    gemm_f16<<<dim3(DMODEL / 128, MROWS / 128), 128, G_SMEM>>>(out, DMODEL, 0);
}

// round 16
// speedup vs baseline: 2.4451x; 1.0115x over previous
#include <cuda_runtime.h>
#include <cuda_fp16.h>
#include <cstdint>

#define HEADS   16
#define DH      64
#define SEQT    2048
#define BATCH   4
#define DMODEL  1024
#define KDIM    1024
#define BHEADS  (BATCH * HEADS)   // 64
#define MROWS   (BATCH * SEQT)    // 8192

__device__ __half g_qh[(size_t)BHEADS * SEQT * DH];          // [bh][t][dh]
__device__ __half g_kh[(size_t)BHEADS * SEQT * DH];          // [bh][t][dh]
__device__ __half g_vT[(size_t)BHEADS * DH * SEQT];          // [bh][dh][t]
__device__ __half g_oh[(size_t)MROWS * DMODEL];              // [m][1024]
__device__ __half g_xh[(size_t)MROWS * DMODEL];              // rounded x
__device__ __half g_wqT[(size_t)3 * DMODEL * DMODEL];        // [3072][1024] n-major
__device__ __half g_woT[(size_t)DMODEL * DMODEL];            // [1024][1024] n-major

// ---------------- helpers ----------------
__device__ __forceinline__ unsigned pack_f16x2(float lo, float hi) {
    unsigned d;
    asm("cvt.rn.f16x2.f32 %0, %1, %2;" : "=r"(d) : "f"(hi), "f"(lo));
    return d;
}
__device__ __forceinline__ uint32_t smem_u32(const void* p) {
    uint32_t a;
    asm("{ .reg .u64 t; cvta.to.shared.u64 t, %1; cvt.u32.u64 %0, t; }"
        : "=r"(a) : "l"(p));
    return a;
}

#define CP16(dst, src) \
    asm volatile("cp.async.cg.shared.global [%0], [%1], 16;" \
                 :: "r"(dst), "l"(src) : "memory")
#define CP_COMMIT() asm volatile("cp.async.commit_group;" ::: "memory")
#define CP_WAIT1()  asm volatile("cp.async.wait_group 1;" ::: "memory")
#define CP_WAIT0()  asm volatile("cp.async.wait_group 0;" ::: "memory")

// m16n8k16 fp16 mma, fp32 accumulate
__device__ __forceinline__ void mma_f16(float* c, const unsigned* a,
                                        unsigned b0, unsigned b1) {
    asm volatile(
        "mma.sync.aligned.m16n8k16.row.col.f32.f16.f16.f32 "
        "{%0,%1,%2,%3},{%4,%5,%6,%7},{%8,%9},{%0,%1,%2,%3};\n"
        : "+f"(c[0]), "+f"(c[1]), "+f"(c[2]), "+f"(c[3])
        : "r"(a[0]), "r"(a[1]), "r"(a[2]), "r"(a[3]), "r"(b0), "r"(b1));
}

// ldmatrix x4: 4 fragment regs in one LSU op
__device__ __forceinline__ void ldsm_x4(unsigned* r, uint32_t addr) {
    asm volatile(
        "ldmatrix.sync.aligned.m8n8.x4.shared.b16 {%0,%1,%2,%3}, [%4];"
        : "=r"(r[0]), "=r"(r[1]), "=r"(r[2]), "=r"(r[3]) : "r"(addr));
}

// ---------------- prep: fp16 rounding (+ weight transpose to n-major) ------
__global__ void round_xh(const float4* __restrict__ src) {
    int i = blockIdx.x * blockDim.x + threadIdx.x;
    float4 v = src[i];
    uint2 h;
    h.x = pack_f16x2(v.x, v.y);
    h.y = pack_f16x2(v.z, v.w);
    ((uint2*)g_xh)[i] = h;
}
__global__ __launch_bounds__(256) void tr_wq(const float* __restrict__ src) {
    __shared__ float tile[32][33];
    const int n0 = blockIdx.x * 32, k0 = blockIdx.y * 32;
    const int tx = threadIdx.x & 31, ty = threadIdx.x >> 5;
#pragma unroll
    for (int i = ty; i < 32; i += 8)
        tile[i][tx] = src[(size_t)(k0 + i) * (3 * DMODEL) + n0 + tx];
    __syncthreads();
#pragma unroll
    for (int i = ty; i < 32; i += 8)
        g_wqT[(size_t)(n0 + i) * KDIM + k0 + tx] = __float2half_rn(tile[tx][i]);
}
__global__ __launch_bounds__(256) void tr_wo(const float* __restrict__ src) {
    __shared__ float tile[32][33];
    const int n0 = blockIdx.x * 32, k0 = blockIdx.y * 32;
    const int tx = threadIdx.x & 31, ty = threadIdx.x >> 5;
#pragma unroll
    for (int i = ty; i < 32; i += 8)
        tile[i][tx] = src[(size_t)(k0 + i) * DMODEL + n0 + tx];
    __syncthreads();
#pragma unroll
    for (int i = ty; i < 32; i += 8)
        g_woT[(size_t)(n0 + i) * KDIM + k0 + tx] = __float2half_rn(tile[tx][i]);
}

// ---------------------------------------------------------------------------
// GEMM fp16 + LDSM + 3-stage ring (wait_group 1 steady state).
// BM=BN=128, BK=32, 128 thr (4 warps 2x2), warp 64x64, launch_bounds(128,3).
// ---------------------------------------------------------------------------
#define BK      32
#define STRH    40                         // halfs per smem row (80B)
#define TILE_B  (128 * STRH * 2)           // 10240 B per A or B tile
#define STG_B   (2 * TILE_B)               // 20480 B per stage
#define G_SMEM  (3 * STG_B)                // 61440 B -> 3 CTAs/SM

__device__ __forceinline__ void g_load_slice(uint32_t sbase,
                                             const __half* __restrict__ A,
                                             const __half* __restrict__ B,
                                             int bm, int bn, int kt, int tid) {
    const uint32_t sa = sbase;
    const uint32_t sb = sbase + TILE_B;
#pragma unroll
    for (int p = 0; p < 4; p++) {
        int idx = tid + 128 * p;
        int r = idx >> 2, c = idx & 3;
        CP16(sa + r * 80 + c * 16,
             A + (size_t)(bm * 128 + r) * KDIM + kt * 32 + c * 8);
    }
#pragma unroll
    for (int p = 0; p < 4; p++) {
        int idx = tid + 128 * p;
        int n = idx >> 2, c = idx & 3;
        CP16(sb + n * 80 + c * 16,
             B + (size_t)(bn * 128 + n) * KDIM + kt * 32 + c * 8);
    }
}

__global__ __launch_bounds__(128, 3) void gemm_f16(float* __restrict__ C, int N,
                                                   int mode) {
    extern __shared__ __half smh[];
    const uint32_t sm0 = smem_u32(smh);

    const int tid = threadIdx.x, lane = tid & 31, wid = tid >> 5;
    const int wm = wid >> 1, wn = wid & 1;
    const int bn = blockIdx.x, bm = blockIdx.y;

    const __half* A = mode ? g_xh : g_oh;
    const __half* B = mode ? g_wqT : g_woT;

    const uint32_t a_lane = ((lane & 15) * STRH + ((lane >> 4) & 1) * 8) * 2;
    const uint32_t b_lane = ((((lane >> 4) & 1) * 8 + (lane & 7)) * STRH
                             + ((lane >> 3) & 1) * 8) * 2;

    float acc[4][8][4];
#pragma unroll
    for (int mt = 0; mt < 4; mt++)
#pragma unroll
        for (int nt = 0; nt < 8; nt++)
#pragma unroll
            for (int i = 0; i < 4; i++) acc[mt][nt][i] = 0.f;

    // prologue: slices 0,1 into stages 0,1 (prefetch distance 2)
    g_load_slice(sm0 + 0 * STG_B, A, B, bm, bn, 0, tid); CP_COMMIT();
    g_load_slice(sm0 + 1 * STG_B, A, B, bm, bn, 1, tid); CP_COMMIT();

    const int NSL = KDIM / BK;   // 32
    for (int j = 0; j < NSL; j++) {
        if (j < NSL - 1) { CP_WAIT1(); } else { CP_WAIT0(); }
        __syncthreads();
        if (j + 2 < NSL) {
            g_load_slice(sm0 + ((j + 2) % 3) * STG_B, A, B, bm, bn, j + 2, tid);
            CP_COMMIT();
        }

        const uint32_t as0 = sm0 + (j % 3) * STG_B;
        const uint32_t bs0 = as0 + TILE_B;
#pragma unroll
        for (int kc = 0; kc < 2; kc++) {
            const uint32_t kb2 = kc * 16 * 2;
            unsigned a[4][4];
#pragma unroll
            for (int mt = 0; mt < 4; mt++)
                ldsm_x4(a[mt], as0 + (wm * 64 + mt * 16) * (STRH * 2) + kb2 + a_lane);
            unsigned b[8][2];
#pragma unroll
            for (int ntp = 0; ntp < 4; ntp++) {
                unsigned r[4];
                ldsm_x4(r, bs0 + (wn * 64 + ntp * 16) * (STRH * 2) + kb2 + b_lane);
                b[2 * ntp][0] = r[0]; b[2 * ntp][1] = r[1];
                b[2 * ntp + 1][0] = r[2]; b[2 * ntp + 1][1] = r[3];
            }
#pragma unroll
            for (int mt = 0; mt < 4; mt++)
#pragma unroll
                for (int nt = 0; nt < 8; nt++)
                    mma_f16(acc[mt][nt], a[mt], b[nt][0], b[nt][1]);
        }
    }

    // epilogue
#pragma unroll
    for (int mt = 0; mt < 4; mt++) {
#pragma unroll
        for (int nt = 0; nt < 8; nt++) {
            int rbase = bm * 128 + wm * 64 + mt * 16 + (lane >> 2);
            int cbase = bn * 128 + wn * 64 + nt * 8 + 2 * (lane & 3);
#pragma unroll
            for (int i = 0; i < 4; i++) {
                int rr = rbase + ((i >= 2) ? 8 : 0);
                int cc = cbase + (i & 1);
                float v = acc[mt][nt][i];
                if (mode == 0) {
                    C[(size_t)rr * N + cc] = v;
                } else {
                    int b_ = rr >> 11, t = rr & 2047;
                    int which = cc >> 10, rem = cc & 1023;
                    int h = rem >> 6, dd = rem & 63;
                    size_t bh = (size_t)(b_ * HEADS + h);
                    __half hv = __float2half_rn(v);
                    if (which == 0)      g_qh[(bh * SEQT + t) * DH + dd] = hv;
                    else if (which == 1) g_kh[(bh * SEQT + t) * DH + dd] = hv;
                    else                 g_vT[(bh * DH + dd) * SEQT + t] = hv;
                }
            }
        }
    }
}

// ---------------------------------------------------------------------------
// Flash attention fp16 + LDSM + 3-stage K/V ring (wait_group 1).
// Grid (bh=64, qt=16), 256 thr / 8 warps, warp = 16 q rows.
// launch_bounds(256,2); 55.3KB smem -> 2 CTAs/SM.
// ---------------------------------------------------------------------------
#define KSTH   72
#define KT_B   (64 * KSTH * 2)            // 9216 B per K or V tile
#define FL_SMEM (3 * 2 * KT_B)            // 55,296 B

__device__ __forceinline__ void fl_issue_kv(uint32_t kbase, uint32_t vbase,
                                            const __half* __restrict__ Kg,
                                            const __half* __restrict__ Vt,
                                            int tile, int tid) {
#pragma unroll
    for (int p = 0; p < 2; p++) {
        int idx = tid + 256 * p;
        int row = idx >> 3, c = idx & 7;
        CP16(kbase + row * 144 + c * 16,
             Kg + (size_t)(tile * 64 + row) * DH + c * 8);
    }
#pragma unroll
    for (int p = 0; p < 2; p++) {
        int idx = tid + 256 * p;
        int row = idx >> 3, c = idx & 7;
        CP16(vbase + row * 144 + c * 16,
             Vt + (size_t)row * SEQT + tile * 64 + c * 8);
    }
}

__global__ __launch_bounds__(256, 2) void flash_attn() {
    extern __shared__ __half smh[];
    const uint32_t sm0 = smem_u32(smh);
    const uint32_t kbase0 = sm0;                  // 3 K stages
    const uint32_t vbase0 = sm0 + 3 * KT_B;       // 3 V stages

    const int bh = blockIdx.x, qt = blockIdx.y;
    const int tid = threadIdx.x, lane = tid & 31, w = tid >> 5;

    const __half* Qg = g_qh + ((size_t)bh * SEQT + qt * 128) * DH;
    const __half* Kg = g_kh + (size_t)bh * SEQT * DH;
    const __half* Vt = g_vT + (size_t)bh * DH * SEQT;

    // prologue: tiles 0,1
    fl_issue_kv(kbase0 + 0 * KT_B, vbase0 + 0 * KT_B, Kg, Vt, 0, tid); CP_COMMIT();
    fl_issue_kv(kbase0 + 1 * KT_B, vbase0 + 1 * KT_B, Kg, Vt, 1, tid); CP_COMMIT();

    const uint32_t kv_lane = ((((lane >> 4) & 1) * 8 + (lane & 7)) * KSTH
                              + ((lane >> 3) & 1) * 8) * 2;

    // ---- Q fragments in registers ----
    unsigned qf[4][4];
    {
        const int r = w * 16 + (lane >> 2);
#pragma unroll
        for (int kc = 0; kc < 4; kc++) {
            const int kb = kc * 16 + 2 * (lane & 3);
            qf[kc][0] = *(const unsigned*)&Qg[(size_t)r * DH + kb];
            qf[kc][1] = *(const unsigned*)&Qg[(size_t)(r + 8) * DH + kb];
            qf[kc][2] = *(const unsigned*)&Qg[(size_t)r * DH + kb + 8];
            qf[kc][3] = *(const unsigned*)&Qg[(size_t)(r + 8) * DH + kb + 8];
        }
    }

    float m[2] = {-1e30f, -1e30f}, l[2] = {0.f, 0.f};
    float o[8][4];
#pragma unroll
    for (int nt = 0; nt < 8; nt++)
#pragma unroll
        for (int i = 0; i < 4; i++) o[nt][i] = 0.f;

    const float SCALE2 = 0.03125f * 1.4426950408889634f;  // 1024^-0.5 * log2(e)

    for (int j = 0; j < 32; j++) {
        if (j < 31) { CP_WAIT1(); } else { CP_WAIT0(); }
        __syncthreads();
        if (j + 2 < 32) {
            int sp = (j + 2) % 3;
            fl_issue_kv(kbase0 + sp * KT_B, vbase0 + sp * KT_B, Kg, Vt, j + 2, tid);
            CP_COMMIT();
        }
        const uint32_t kc0 = kbase0 + (j % 3) * KT_B;
        const uint32_t vc0 = vbase0 + (j % 3) * KT_B;

        // ---- S = Q @ K^T ----
        float s[8][4];
#pragma unroll
        for (int nt = 0; nt < 8; nt++) {
            s[nt][0] = s[nt][1] = s[nt][2] = s[nt][3] = 0.f;
        }
#pragma unroll
        for (int kc = 0; kc < 4; kc++) {
            const uint32_t kb2 = kc * 16 * 2;
#pragma unroll
            for (int ntp = 0; ntp < 4; ntp++) {
                unsigned r[4];
                ldsm_x4(r, kc0 + (ntp * 16) * (KSTH * 2) + kb2 + kv_lane);
                mma_f16(s[2 * ntp],     qf[kc], r[0], r[1]);
                mma_f16(s[2 * ntp + 1], qf[kc], r[2], r[3]);
            }
        }

        // ---- online max (exp2 domain) ----
        float mx[2] = {m[0], m[1]};
#pragma unroll
        for (int nt = 0; nt < 8; nt++) {
            s[nt][0] *= SCALE2; s[nt][1] *= SCALE2;
            s[nt][2] *= SCALE2; s[nt][3] *= SCALE2;
            mx[0] = fmaxf(mx[0], fmaxf(s[nt][0], s[nt][1]));
            mx[1] = fmaxf(mx[1], fmaxf(s[nt][2], s[nt][3]));
        }
#pragma unroll
        for (int hh = 0; hh < 2; hh++) {
            mx[hh] = fmaxf(mx[hh], __shfl_xor_sync(0xffffffffu, mx[hh], 1));
            mx[hh] = fmaxf(mx[hh], __shfl_xor_sync(0xffffffffu, mx[hh], 2));
        }
        float alpha[2];
#pragma unroll
        for (int hh = 0; hh < 2; hh++) {
            alpha[hh] = exp2f(m[hh] - mx[hh]);
            m[hh] = mx[hh];
        }
#pragma unroll
        for (int nt = 0; nt < 8; nt++) {
            o[nt][0] *= alpha[0]; o[nt][1] *= alpha[0];
            o[nt][2] *= alpha[1]; o[nt][3] *= alpha[1];
        }

        // ---- PV: exp + f16x2 pack; V frags via LDSM ----
        float sum[2] = {0.f, 0.f};
#pragma unroll
        for (int kc = 0; kc < 4; kc++) {
            float pA0 = exp2f(s[2 * kc][0] - mx[0]);
            float pA1 = exp2f(s[2 * kc][1] - mx[0]);
            float pA2 = exp2f(s[2 * kc][2] - mx[1]);
            float pA3 = exp2f(s[2 * kc][3] - mx[1]);
            float pB0 = exp2f(s[2 * kc + 1][0] - mx[0]);
            float pB1 = exp2f(s[2 * kc + 1][1] - mx[0]);
            float pB2 = exp2f(s[2 * kc + 1][2] - mx[1]);
            float pB3 = exp2f(s[2 * kc + 1][3] - mx[1]);
            sum[0] += pA0 + pA1 + pB0 + pB1;
            sum[1] += pA2 + pA3 + pB2 + pB3;
            unsigned aP[4];
            aP[0] = pack_f16x2(pA0, pA1);
            aP[1] = pack_f16x2(pA2, pA3);
            aP[2] = pack_f16x2(pB0, pB1);
            aP[3] = pack_f16x2(pB2, pB3);
            const uint32_t kb2 = kc * 16 * 2;
#pragma unroll
            for (int ntp = 0; ntp < 4; ntp++) {
                unsigned r[4];
                ldsm_x4(r, vc0 + (ntp * 16) * (KSTH * 2) + kb2 + kv_lane);
                mma_f16(o[2 * ntp],     aP, r[0], r[1]);
                mma_f16(o[2 * ntp + 1], aP, r[2], r[3]);
            }
        }
        // quad-reduce row sums, fold into l
#pragma unroll
        for (int hh = 0; hh < 2; hh++) {
            sum[hh] += __shfl_xor_sync(0xffffffffu, sum[hh], 1);
            sum[hh] += __shfl_xor_sync(0xffffffffu, sum[hh], 2);
            l[hh] = l[hh] * alpha[hh] + sum[hh];
        }
    }

    // ---- epilogue: normalize, write g_oh ----
    const int b = bh >> 4, hd = bh & 15;
    const float inv0 = 1.f / l[0], inv1 = 1.f / l[1];
    size_t row0 = (size_t)b * SEQT + qt * 128 + w * 16 + (lane >> 2);
#pragma unroll
    for (int nt = 0; nt < 8; nt++) {
        int cc = hd * DH + nt * 8 + 2 * (lane & 3);
        g_oh[row0 * DMODEL + cc]           = __float2half_rn(o[nt][0] * inv0);
        g_oh[row0 * DMODEL + cc + 1]       = __float2half_rn(o[nt][1] * inv0);
        g_oh[(row0 + 8) * DMODEL + cc]     = __float2half_rn(o[nt][2] * inv1);
        g_oh[(row0 + 8) * DMODEL + cc + 1] = __float2half_rn(o[nt][3] * inv1);
    }
}

// ---------------------------------------------------------------------------
extern "C" void kernel_launch(void* const* d_in, const int* in_sizes, int n_in,
                              void* d_out, int out_size) {
    const float* x     = (const float*)d_in[0];  // [4,2048,1024]
    const float* w_qkv = (const float*)d_in[1];  // [1024,3072]
    const float* w_out = (const float*)d_in[2];  // [1024,1024]
    float* out = (float*)d_out;                  // [4,2048,1024]

    round_xh<<<MROWS * DMODEL / 4 / 256, 256>>>((const float4*)x);
    tr_wq<<<dim3(3 * DMODEL / 32, DMODEL / 32), 256>>>(w_qkv);
    tr_wo<<<dim3(DMODEL / 32, DMODEL / 32), 256>>>(w_out);

    cudaFuncSetAttribute(gemm_f16, cudaFuncAttributeMaxDynamicSharedMemorySize,
                         G_SMEM);
    cudaFuncSetAttribute(flash_attn, cudaFuncAttributeMaxDynamicSharedMemorySize,
                         FL_SMEM);

    // K1: QKV projection, scatter epilogue (V transposed for flash PV)
    gemm_f16<<<dim3(3 * DMODEL / 128, MROWS / 128), 128, G_SMEM>>>(nullptr,
                                                                   3 * DMODEL, 1);
    // K2: flash attention
    flash_attn<<<dim3(BHEADS, SEQT / 128), 256, FL_SMEM>>>();

    // K3: output projection
    gemm_f16<<<dim3(DMODEL / 128, MROWS / 128), 128, G_SMEM>>>(out, DMODEL, 0);
}